// round 2
// baseline (speedup 1.0000x reference)
#include <cuda_runtime.h>
#include <cuda_bf16.h>
#include <math.h>

#define NN 20000
#define HH 256
#define EE 320000

// ---------------- scratch (device globals; no allocation allowed) ----------------
__device__ float g_ns[(size_t)NN * HH];
__device__ float g_ns2[(size_t)NN * HH];
__device__ float g_h[(size_t)NN * HH];
__device__ float g_av[NN];
__device__ float g_bv[NN];
__device__ int   g_deg[NN];
__device__ int   g_rowptr[NN + 1];
__device__ int   g_cursor[NN];
__device__ int   g_src_s[EE];
__device__ int   g_dst_s[EE];
__device__ float g_scores[EE];
__device__ float g_attn[EE];
__device__ unsigned g_maxenc[4];
__device__ float g_pool_sum;

// order-preserving float<->uint map for atomicMax on floats (handles negatives)
__device__ __forceinline__ unsigned enc_f(float x) {
    unsigned u = __float_as_uint(x);
    return (u & 0x80000000u) ? ~u : (u | 0x80000000u);
}
__device__ __forceinline__ float dec_f(unsigned u) {
    return (u & 0x80000000u) ? __uint_as_float(u & 0x7fffffffu)
                             : __uint_as_float(~u);
}

__device__ __forceinline__ float blk_sum(float v) {
    __shared__ float sh[32];
    int lane = threadIdx.x & 31, w = threadIdx.x >> 5;
#pragma unroll
    for (int o = 16; o; o >>= 1) v += __shfl_down_sync(0xffffffffu, v, o);
    if (!lane) sh[w] = v;
    __syncthreads();
    int nw = blockDim.x >> 5;
    float r = (threadIdx.x < nw) ? sh[threadIdx.x] : 0.f;
    if (w == 0) {
#pragma unroll
        for (int o = 16; o; o >>= 1) r += __shfl_down_sync(0xffffffffu, r, o);
        if (!lane) sh[0] = r;
    }
    __syncthreads();
    r = sh[0];
    __syncthreads();
    return r;
}

// ---------------- setup kernels ----------------
__global__ void init_kernel(float* out) {
    int i = blockIdx.x * blockDim.x + threadIdx.x;
    if (i < NN) g_deg[i] = 0;
    if (blockIdx.x == 0) {
        if (threadIdx.x < 4) g_maxenc[threadIdx.x] = 0x007FFFFFu; // enc(-inf)
        if (threadIdx.x == 4) g_pool_sum = 0.f;
        if (threadIdx.x < HH) out[threadIdx.x] = 0.f; // graph_vec accum region
    }
}

__global__ void deg_kernel(const int* __restrict__ dst) {
    int e = blockIdx.x * blockDim.x + threadIdx.x;
    if (e < EE) atomicAdd(&g_deg[dst[e]], 1);
}

// single-block exclusive scan over g_deg -> g_rowptr, g_cursor
__global__ void scan_kernel() {
    __shared__ int ssum[1024];
    const int CH = (NN + 1023) / 1024; // 20
    int tid = threadIdx.x;
    int start = tid * CH;
    int local[32];
    int s = 0;
#pragma unroll
    for (int i = 0; i < CH; i++) {
        int idx = start + i;
        int d = (idx < NN) ? g_deg[idx] : 0;
        local[i] = s;
        s += d;
    }
    ssum[tid] = s;
    __syncthreads();
    for (int off = 1; off < 1024; off <<= 1) {
        int v = 0;
        if (tid >= off) v = ssum[tid - off];
        __syncthreads();
        if (tid >= off) ssum[tid] += v;
        __syncthreads();
    }
    int prefix = ssum[tid] - s; // exclusive
#pragma unroll
    for (int i = 0; i < CH; i++) {
        int idx = start + i;
        if (idx < NN) {
            int p = prefix + local[i];
            g_rowptr[idx] = p;
            g_cursor[idx] = p;
        }
    }
    if (tid == 1023) g_rowptr[NN] = ssum[1023];
}

__global__ void scatter_kernel(const int* __restrict__ src, const int* __restrict__ dst) {
    int e = blockIdx.x * blockDim.x + threadIdx.x;
    if (e < EE) {
        int d = dst[e];
        int pos = atomicAdd(&g_cursor[d], 1);
        g_src_s[pos] = src[e];
        g_dst_s[pos] = d;
    }
}

__global__ void embed_kernel(const int* __restrict__ node_ids, const float* __restrict__ emb) {
    int n = blockIdx.x;
    int t = threadIdx.x;
    g_ns[(size_t)n * HH + t] = emb[(size_t)node_ids[n] * HH + t];
}

// ---------------- SGEMM: C[M,256] = A[M,256] * B[256,256]^T ----------------
#define BM 128
#define BN 128
#define BKK 16
__global__ __launch_bounds__(256) void sgemm_nt(const float* __restrict__ A,
                                                const float* __restrict__ B,
                                                float* __restrict__ C, int M) {
    __shared__ float As[BKK][BM];
    __shared__ float Bs[BKK][BN];
    int bm = blockIdx.x * BM;
    int bn = blockIdx.y * BN;
    int tid = threadIdx.x;
    int tx = tid & 15, ty = tid >> 4;
    float acc[8][8];
#pragma unroll
    for (int i = 0; i < 8; i++)
#pragma unroll
        for (int j = 0; j < 8; j++) acc[i][j] = 0.f;

    for (int k0 = 0; k0 < HH; k0 += BKK) {
#pragma unroll
        for (int i = 0; i < 2; i++) {
            int li = tid + i * 256;
            int row = li >> 2;
            int c4 = li & 3;
            int gr = bm + row;
            float4 v = make_float4(0.f, 0.f, 0.f, 0.f);
            if (gr < M) v = *(const float4*)&A[(size_t)gr * HH + k0 + c4 * 4];
            As[c4 * 4 + 0][row] = v.x;
            As[c4 * 4 + 1][row] = v.y;
            As[c4 * 4 + 2][row] = v.z;
            As[c4 * 4 + 3][row] = v.w;
        }
#pragma unroll
        for (int i = 0; i < 2; i++) {
            int li = tid + i * 256;
            int row = li >> 2;
            int c4 = li & 3;
            float4 v = *(const float4*)&B[(size_t)(bn + row) * HH + k0 + c4 * 4];
            Bs[c4 * 4 + 0][row] = v.x;
            Bs[c4 * 4 + 1][row] = v.y;
            Bs[c4 * 4 + 2][row] = v.z;
            Bs[c4 * 4 + 3][row] = v.w;
        }
        __syncthreads();
#pragma unroll
        for (int k = 0; k < BKK; k++) {
            float ar[8], br[8];
            float4 a0 = *(float4*)&As[k][ty * 8];
            float4 a1 = *(float4*)&As[k][ty * 8 + 4];
            float4 b0 = *(float4*)&Bs[k][tx * 8];
            float4 b1 = *(float4*)&Bs[k][tx * 8 + 4];
            ar[0] = a0.x; ar[1] = a0.y; ar[2] = a0.z; ar[3] = a0.w;
            ar[4] = a1.x; ar[5] = a1.y; ar[6] = a1.z; ar[7] = a1.w;
            br[0] = b0.x; br[1] = b0.y; br[2] = b0.z; br[3] = b0.w;
            br[4] = b1.x; br[5] = b1.y; br[6] = b1.z; br[7] = b1.w;
#pragma unroll
            for (int i = 0; i < 8; i++)
#pragma unroll
                for (int j = 0; j < 8; j++) acc[i][j] = fmaf(ar[i], br[j], acc[i][j]);
        }
        __syncthreads();
    }
#pragma unroll
    for (int i = 0; i < 8; i++) {
        int row = bm + ty * 8 + i;
        if (row < M) {
#pragma unroll
            for (int j = 0; j < 2; j++) {
                float4 v = make_float4(acc[i][j * 4], acc[i][j * 4 + 1], acc[i][j * 4 + 2], acc[i][j * 4 + 3]);
                *(float4*)&C[(size_t)row * HH + bn + tx * 8 + j * 4] = v;
            }
        }
    }
}

// ---------------- per-layer kernels ----------------
// a[n] = h[n]·ew[:H], b[n] = h[n]·ew[H:]
__global__ void ab_kernel(const float* __restrict__ hbuf, const float* __restrict__ ew) {
    int wg = (blockIdx.x * blockDim.x + threadIdx.x) >> 5;
    int lane = threadIdx.x & 31;
    if (wg >= NN) return;
    const float* row = hbuf + (size_t)wg * HH;
    float a = 0.f, b = 0.f;
#pragma unroll
    for (int k = lane; k < HH; k += 32) {
        float hv = row[k];
        a = fmaf(hv, ew[k], a);
        b = fmaf(hv, ew[HH + k], b);
    }
#pragma unroll
    for (int o = 16; o; o >>= 1) {
        a += __shfl_down_sync(0xffffffffu, a, o);
        b += __shfl_down_sync(0xffffffffu, b, o);
    }
    if (!lane) { g_av[wg] = a; g_bv[wg] = b; }
}

__global__ void scores_kernel(int slot) {
    __shared__ float sh[32];
    int i = blockIdx.x * blockDim.x + threadIdx.x;
    float s = -3.4e38f;
    if (i < EE) {
        float v = g_av[g_src_s[i]] + g_bv[g_dst_s[i]];
        v = (v >= 0.f) ? v : 0.2f * v;
        g_scores[i] = v;
        s = v;
    }
    // block max
    int lane = threadIdx.x & 31, w = threadIdx.x >> 5;
#pragma unroll
    for (int o = 16; o; o >>= 1) s = fmaxf(s, __shfl_down_sync(0xffffffffu, s, o));
    if (!lane) sh[w] = s;
    __syncthreads();
    if (threadIdx.x == 0) {
        float m = sh[0];
        for (int k = 1; k < (int)(blockDim.x >> 5); k++) m = fmaxf(m, sh[k]);
        atomicMax(&g_maxenc[slot], enc_f(m));
    }
}

// fused: denom -> weighted gather-sum -> residual -> LayerNorm -> GELU(exact)
__global__ __launch_bounds__(HH) void agg_kernel(const float* __restrict__ hbuf,
                                                 const float* __restrict__ nsin,
                                                 float* __restrict__ nsout,
                                                 const float* __restrict__ gamma,
                                                 const float* __restrict__ beta,
                                                 int slot) {
    int n = blockIdx.x;
    int tid = threadIdx.x;
    int beg = g_rowptr[n], end = g_rowptr[n + 1];
    float smax = dec_f(g_maxenc[slot]);
    float local = 0.f;
    for (int i = beg + tid; i < end; i += HH) {
        float w = expf(g_scores[i] - smax);
        g_attn[i] = w;
        local += w;
    }
    float denom = blk_sum(local) + 1e-6f;
    float inv = 1.f / denom;
    float acc = 0.f;
    for (int i = beg; i < end; i++) {
        float w = g_attn[i] * inv;      // uniform load -> broadcast
        int s = g_src_s[i];             // uniform load
        acc = fmaf(hbuf[(size_t)s * HH + tid], w, acc);
    }
    float x = acc + nsin[(size_t)n * HH + tid];
    float m = blk_sum(x) * (1.f / HH);
    float d = x - m;
    float var = blk_sum(d * d) * (1.f / HH);
    float y = d * rsqrtf(var + 1e-5f) * gamma[tid] + beta[tid];
    float out = 0.5f * y * (1.f + erff(y * 0.70710678118654752440f));
    nsout[(size_t)n * HH + tid] = out;
}

// ---------------- pooling ----------------
__global__ __launch_bounds__(HH) void pool_s_kernel(const float* __restrict__ P,
                                                    const float* __restrict__ pb,
                                                    const float* __restrict__ sw,
                                                    const int* __restrict__ node_ids) {
    int n = blockIdx.x;
    int tid = threadIdx.x;
    float val = tanhf(P[(size_t)n * HH + tid] + pb[tid]) * sw[tid];
    float s = blk_sum(val);
    if (tid == 0) {
        if (node_ids[n] != 0) {
            g_av[n] = s;
            atomicMax(&g_maxenc[2], enc_f(s));
        } else {
            g_av[n] = 0.f;
        }
    }
}

__global__ void pool_exp_kernel(const int* __restrict__ node_ids) {
    int i = blockIdx.x * blockDim.x + threadIdx.x;
    float e = 0.f;
    if (i < NN) {
        float smax = dec_f(g_maxenc[2]);
        if (node_ids[i] != 0) e = expf(g_av[i] - smax);
        g_bv[i] = e;
    }
    float r = blk_sum(e);
    if (threadIdx.x == 0) atomicAdd(&g_pool_sum, r);
}

// writes w to out[256..] and accumulates graph_vec into out[0..255]
#define FCHUNK 64
__global__ __launch_bounds__(HH) void final_kernel(const float* __restrict__ ns, float* __restrict__ out) {
    int base = blockIdx.x * FCHUNK;
    int tid = threadIdx.x;
    float sum = g_pool_sum;
    float inv = (sum > 0.f) ? 1.f / sum : 0.f;
    if (tid < FCHUNK) {
        int n = base + tid;
        if (n < NN) out[HH + n] = g_bv[n] * inv;
    }
    float acc = 0.f;
    for (int i = 0; i < FCHUNK; i++) {
        int n = base + i;
        if (n >= NN) break;
        float w = g_bv[n] * inv;
        acc = fmaf(w, ns[(size_t)n * HH + tid], acc);
    }
    atomicAdd(&out[tid], acc);
}

// ---------------- launcher ----------------
extern "C" void kernel_launch(void* const* d_in, const int* in_sizes, int n_in,
                              void* d_out, int out_size) {
    const int*   node_ids = (const int*)d_in[0];
    const int*   edge_index = (const int*)d_in[1];
    const float* emb    = (const float*)d_in[2];
    const float* proj_w = (const float*)d_in[3];
    const float* edge_w = (const float*)d_in[4];
    const float* ln_g   = (const float*)d_in[5];
    const float* ln_b   = (const float*)d_in[6];
    const float* pool_w = (const float*)d_in[7];
    const float* pool_b = (const float*)d_in[8];
    const float* score_w = (const float*)d_in[9];
    float* out = (float*)d_out;
    const int* src = edge_index;
    const int* dst = edge_index + EE;

    float *p_ns, *p_ns2, *p_h;
    cudaGetSymbolAddress((void**)&p_ns, g_ns);
    cudaGetSymbolAddress((void**)&p_ns2, g_ns2);
    cudaGetSymbolAddress((void**)&p_h, g_h);

    init_kernel<<<(NN + 255) / 256, 256>>>(out);
    deg_kernel<<<(EE + 255) / 256, 256>>>(dst);
    scan_kernel<<<1, 1024>>>();
    scatter_kernel<<<(EE + 255) / 256, 256>>>(src, dst);
    embed_kernel<<<NN, HH>>>(node_ids, emb);

    dim3 gemm_grid((NN + BM - 1) / BM, HH / BN);

    // layer 0
    sgemm_nt<<<gemm_grid, 256>>>(p_ns, proj_w, p_h, NN);
    ab_kernel<<<(NN * 32 + 255) / 256, 256>>>(p_h, edge_w);
    scores_kernel<<<(EE + 255) / 256, 256>>>(0);
    agg_kernel<<<NN, HH>>>(p_h, p_ns, p_ns2, ln_g, ln_b, 0);

    // layer 1
    sgemm_nt<<<gemm_grid, 256>>>(p_ns2, proj_w + HH * HH, p_h, NN);
    ab_kernel<<<(NN * 32 + 255) / 256, 256>>>(p_h, edge_w + 2 * HH);
    scores_kernel<<<(EE + 255) / 256, 256>>>(1);
    agg_kernel<<<NN, HH>>>(p_h, p_ns2, p_ns, ln_g + HH, ln_b + HH, 1);

    // pooling
    sgemm_nt<<<gemm_grid, 256>>>(p_ns, pool_w, p_h, NN);
    pool_s_kernel<<<NN, HH>>>(p_h, pool_b, score_w, node_ids);
    pool_exp_kernel<<<(NN + 255) / 256, 256>>>(node_ids);
    final_kernel<<<(NN + FCHUNK - 1) / FCHUNK, HH>>>(p_ns, out);
}

// round 5
// speedup vs baseline: 1.4945x; 1.4945x over previous
#include <cuda_runtime.h>
#include <cuda_bf16.h>
#include <math.h>
#include <stdint.h>

#define NN 20000
#define HH 256
#define EE 320000

// ---------------- scratch (device globals; no allocation allowed) ----------------
__device__ float g_ns[(size_t)NN * HH];
__device__ float g_ns2[(size_t)NN * HH];
__device__ float g_h[(size_t)NN * HH];
__device__ float g_av[NN];
__device__ float g_bv[NN];
__device__ int   g_deg[NN];
__device__ int   g_rowptr[NN + 1];
__device__ int   g_cursor[NN];
__device__ int   g_src_s[EE];
__device__ int   g_dst_s[EE];
__device__ float g_scores[EE];
__device__ float g_attn[EE];
__device__ unsigned g_maxenc[4];
__device__ float g_pool_sum;

// order-preserving float<->uint map for atomicMax on floats
__device__ __forceinline__ unsigned enc_f(float x) {
    unsigned u = __float_as_uint(x);
    return (u & 0x80000000u) ? ~u : (u | 0x80000000u);
}
__device__ __forceinline__ float dec_f(unsigned u) {
    return (u & 0x80000000u) ? __uint_as_float(u & 0x7fffffffu)
                             : __uint_as_float(~u);
}

__device__ __forceinline__ float blk_sum(float v) {
    __shared__ float sh[32];
    int lane = threadIdx.x & 31, w = threadIdx.x >> 5;
#pragma unroll
    for (int o = 16; o; o >>= 1) v += __shfl_down_sync(0xffffffffu, v, o);
    if (!lane) sh[w] = v;
    __syncthreads();
    int nw = blockDim.x >> 5;
    float r = (threadIdx.x < nw) ? sh[threadIdx.x] : 0.f;
    if (w == 0) {
#pragma unroll
        for (int o = 16; o; o >>= 1) r += __shfl_down_sync(0xffffffffu, r, o);
        if (!lane) sh[0] = r;
    }
    __syncthreads();
    r = sh[0];
    __syncthreads();
    return r;
}

// ---------------- setup kernels ----------------
__global__ void init_kernel(float* out) {
    int i = blockIdx.x * blockDim.x + threadIdx.x;
    if (i < NN) g_deg[i] = 0;
    if (blockIdx.x == 0) {
        if (threadIdx.x < 4) g_maxenc[threadIdx.x] = 0x007FFFFFu; // enc(-inf)
        if (threadIdx.x == 4) g_pool_sum = 0.f;
        if (threadIdx.x < HH) out[threadIdx.x] = 0.f;
    }
}

__global__ void deg_kernel(const int* __restrict__ dst) {
    int e = blockIdx.x * blockDim.x + threadIdx.x;
    if (e < EE) atomicAdd(&g_deg[dst[e]], 1);
}

__global__ void scan_kernel() {
    __shared__ int ssum[1024];
    const int CH = (NN + 1023) / 1024; // 20
    int tid = threadIdx.x;
    int start = tid * CH;
    int local[32];
    int s = 0;
#pragma unroll
    for (int i = 0; i < CH; i++) {
        int idx = start + i;
        int d = (idx < NN) ? g_deg[idx] : 0;
        local[i] = s;
        s += d;
    }
    ssum[tid] = s;
    __syncthreads();
    for (int off = 1; off < 1024; off <<= 1) {
        int v = 0;
        if (tid >= off) v = ssum[tid - off];
        __syncthreads();
        if (tid >= off) ssum[tid] += v;
        __syncthreads();
    }
    int prefix = ssum[tid] - s;
#pragma unroll
    for (int i = 0; i < CH; i++) {
        int idx = start + i;
        if (idx < NN) {
            int p = prefix + local[i];
            g_rowptr[idx] = p;
            g_cursor[idx] = p;
        }
    }
    if (tid == 1023) g_rowptr[NN] = ssum[1023];
}

__global__ void scatter_kernel(const int* __restrict__ src, const int* __restrict__ dst) {
    int e = blockIdx.x * blockDim.x + threadIdx.x;
    if (e < EE) {
        int d = dst[e];
        int pos = atomicAdd(&g_cursor[d], 1);
        g_src_s[pos] = src[e];
        g_dst_s[pos] = d;
    }
}

__global__ void embed_kernel(const int* __restrict__ node_ids, const float* __restrict__ emb) {
    int n = blockIdx.x;
    int t = threadIdx.x;
    g_ns[(size_t)n * HH + t] = emb[(size_t)node_ids[n] * HH + t];
}

// ---------------- TF32 mma.sync SGEMM: C[M,256] = A[M,256] * B[256,256]^T ----------------
// CTA 128x128, BK=16, 8 warps (2x4), warp tile 64x32 of m16n8k8.
// B is [n][k] row-major == col-major KxN operand of row.col mma (no transpose).
#define SPAD 20  // smem row stride in floats -> conflict-free fragment loads

__device__ __forceinline__ uint32_t f2tf32(float f) {
    uint32_t r;
    asm("cvt.rna.tf32.f32 %0, %1;" : "=r"(r) : "f"(f));
    return r;
}

__device__ __forceinline__ void mma_tf32(float* c, const uint32_t* a, const uint32_t* b) {
    asm volatile(
        "mma.sync.aligned.m16n8k8.row.col.f32.tf32.tf32.f32 "
        "{%0,%1,%2,%3}, {%4,%5,%6,%7}, {%8,%9}, {%0,%1,%2,%3};"
        : "+f"(c[0]), "+f"(c[1]), "+f"(c[2]), "+f"(c[3])
        : "r"(a[0]), "r"(a[1]), "r"(a[2]), "r"(a[3]), "r"(b[0]), "r"(b[1]));
}

__global__ __launch_bounds__(256) void sgemm_mma(const float* __restrict__ A,
                                                 const float* __restrict__ B,
                                                 float* __restrict__ C, int M) {
    __shared__ uint32_t As[128 * SPAD];
    __shared__ uint32_t Bs[128 * SPAD];
    int tid = threadIdx.x;
    int lane = tid & 31, w = tid >> 5;
    int wm = w & 1, wn = w >> 1;           // warp grid 2 (m) x 4 (n)
    int g = lane >> 2, t4 = lane & 3;      // group-id, thread-in-group
    int bm = blockIdx.x * 128, bn = blockIdx.y * 128;

    float c[4][4][4];
#pragma unroll
    for (int mi = 0; mi < 4; mi++)
#pragma unroll
        for (int ni = 0; ni < 4; ni++)
#pragma unroll
            for (int j = 0; j < 4; j++) c[mi][ni][j] = 0.f;

    // each thread loads 2 float4 from A and 2 from B per BK tile
    int s0 = tid, s1 = tid + 256;          // slots in [0,512): row = s>>2, kq = s&3
    int r0 = s0 >> 2, q0 = s0 & 3;
    int r1 = s1 >> 2, q1 = s1 & 3;
    int ga0 = bm + r0, ga1 = bm + r1;

    float4 ra0, ra1, rb0, rb1;
    const float4 z4 = make_float4(0.f, 0.f, 0.f, 0.f);

    // prefetch k-tile 0
    {
        ra0 = (ga0 < M) ? *(const float4*)&A[(size_t)ga0 * HH + q0 * 4] : z4;
        ra1 = (ga1 < M) ? *(const float4*)&A[(size_t)ga1 * HH + q1 * 4] : z4;
        rb0 = *(const float4*)&B[(size_t)(bn + r0) * HH + q0 * 4];
        rb1 = *(const float4*)&B[(size_t)(bn + r1) * HH + q1 * 4];
    }

#pragma unroll 1
    for (int it = 0; it < 16; it++) {
        // store prefetched tile (convert to tf32)
        {
            uint32_t* pa0 = &As[r0 * SPAD + q0 * 4];
            pa0[0] = f2tf32(ra0.x); pa0[1] = f2tf32(ra0.y); pa0[2] = f2tf32(ra0.z); pa0[3] = f2tf32(ra0.w);
            uint32_t* pa1 = &As[r1 * SPAD + q1 * 4];
            pa1[0] = f2tf32(ra1.x); pa1[1] = f2tf32(ra1.y); pa1[2] = f2tf32(ra1.z); pa1[3] = f2tf32(ra1.w);
            uint32_t* pb0 = &Bs[r0 * SPAD + q0 * 4];
            pb0[0] = f2tf32(rb0.x); pb0[1] = f2tf32(rb0.y); pb0[2] = f2tf32(rb0.z); pb0[3] = f2tf32(rb0.w);
            uint32_t* pb1 = &Bs[r1 * SPAD + q1 * 4];
            pb1[0] = f2tf32(rb1.x); pb1[1] = f2tf32(rb1.y); pb1[2] = f2tf32(rb1.z); pb1[3] = f2tf32(rb1.w);
        }
        __syncthreads();

        // prefetch next k-tile
        if (it < 15) {
            int k0 = (it + 1) * 16;
            ra0 = (ga0 < M) ? *(const float4*)&A[(size_t)ga0 * HH + k0 + q0 * 4] : z4;
            ra1 = (ga1 < M) ? *(const float4*)&A[(size_t)ga1 * HH + k0 + q1 * 4] : z4;
            rb0 = *(const float4*)&B[(size_t)(bn + r0) * HH + k0 + q0 * 4];
            rb1 = *(const float4*)&B[(size_t)(bn + r1) * HH + k0 + q1 * 4];
        }

        // compute: 2 k-steps of 8
#pragma unroll
        for (int ks = 0; ks < 2; ks++) {
            int kb = ks * 8 + t4;
            uint32_t af[4][4];
#pragma unroll
            for (int mi = 0; mi < 4; mi++) {
                int rr = wm * 64 + mi * 16 + g;
                af[mi][0] = As[rr * SPAD + kb];
                af[mi][1] = As[(rr + 8) * SPAD + kb];
                af[mi][2] = As[rr * SPAD + kb + 4];
                af[mi][3] = As[(rr + 8) * SPAD + kb + 4];
            }
            uint32_t bf[4][2];
#pragma unroll
            for (int ni = 0; ni < 4; ni++) {
                int cc = wn * 32 + ni * 8 + g;
                bf[ni][0] = Bs[cc * SPAD + kb];
                bf[ni][1] = Bs[cc * SPAD + kb + 4];
            }
#pragma unroll
            for (int mi = 0; mi < 4; mi++)
#pragma unroll
                for (int ni = 0; ni < 4; ni++)
                    mma_tf32(c[mi][ni], af[mi], bf[ni]);
        }
        __syncthreads();
    }

    // epilogue: c0,c1 adjacent cols; c2,c3 adjacent cols 8 rows down
#pragma unroll
    for (int mi = 0; mi < 4; mi++) {
#pragma unroll
        for (int ni = 0; ni < 4; ni++) {
            int row = bm + wm * 64 + mi * 16 + g;
            int col = bn + wn * 32 + ni * 8 + 2 * t4;
            if (row < M)
                *(float2*)&C[(size_t)row * HH + col] = make_float2(c[mi][ni][0], c[mi][ni][1]);
            if (row + 8 < M)
                *(float2*)&C[(size_t)(row + 8) * HH + col] = make_float2(c[mi][ni][2], c[mi][ni][3]);
        }
    }
}

// ---------------- per-layer kernels ----------------
__global__ void ab_kernel(const float* __restrict__ hbuf, const float* __restrict__ ew) {
    int wg = (blockIdx.x * blockDim.x + threadIdx.x) >> 5;
    int lane = threadIdx.x & 31;
    if (wg >= NN) return;
    const float* row = hbuf + (size_t)wg * HH;
    float a = 0.f, b = 0.f;
#pragma unroll
    for (int k = lane; k < HH; k += 32) {
        float hv = row[k];
        a = fmaf(hv, ew[k], a);
        b = fmaf(hv, ew[HH + k], b);
    }
#pragma unroll
    for (int o = 16; o; o >>= 1) {
        a += __shfl_down_sync(0xffffffffu, a, o);
        b += __shfl_down_sync(0xffffffffu, b, o);
    }
    if (!lane) { g_av[wg] = a; g_bv[wg] = b; }
}

__global__ void scores_kernel(int slot) {
    __shared__ float sh[32];
    int i = blockIdx.x * blockDim.x + threadIdx.x;
    float s = -3.4e38f;
    if (i < EE) {
        float v = g_av[g_src_s[i]] + g_bv[g_dst_s[i]];
        v = (v >= 0.f) ? v : 0.2f * v;
        g_scores[i] = v;
        s = v;
    }
    int lane = threadIdx.x & 31, w = threadIdx.x >> 5;
#pragma unroll
    for (int o = 16; o; o >>= 1) s = fmaxf(s, __shfl_down_sync(0xffffffffu, s, o));
    if (!lane) sh[w] = s;
    __syncthreads();
    if (threadIdx.x == 0) {
        float m = sh[0];
        for (int k = 1; k < (int)(blockDim.x >> 5); k++) m = fmaxf(m, sh[k]);
        atomicMax(&g_maxenc[slot], enc_f(m));
    }
}

__global__ __launch_bounds__(HH) void agg_kernel(const float* __restrict__ hbuf,
                                                 const float* __restrict__ nsin,
                                                 float* __restrict__ nsout,
                                                 const float* __restrict__ gamma,
                                                 const float* __restrict__ beta,
                                                 int slot) {
    int n = blockIdx.x;
    int tid = threadIdx.x;
    int beg = g_rowptr[n], end = g_rowptr[n + 1];
    float smax = dec_f(g_maxenc[slot]);
    float local = 0.f;
    for (int i = beg + tid; i < end; i += HH) {
        float w = expf(g_scores[i] - smax);
        g_attn[i] = w;
        local += w;
    }
    float denom = blk_sum(local) + 1e-6f;
    float inv = 1.f / denom;
    float acc = 0.f;
    for (int i = beg; i < end; i++) {
        float w = g_attn[i] * inv;
        int s = g_src_s[i];
        acc = fmaf(hbuf[(size_t)s * HH + tid], w, acc);
    }
    float x = acc + nsin[(size_t)n * HH + tid];
    float m = blk_sum(x) * (1.f / HH);
    float d = x - m;
    float var = blk_sum(d * d) * (1.f / HH);
    float y = d * rsqrtf(var + 1e-5f) * gamma[tid] + beta[tid];
    float out = 0.5f * y * (1.f + erff(y * 0.70710678118654752440f));
    nsout[(size_t)n * HH + tid] = out;
}

// ---------------- pooling ----------------
__global__ __launch_bounds__(HH) void pool_s_kernel(const float* __restrict__ P,
                                                    const float* __restrict__ pb,
                                                    const float* __restrict__ sw,
                                                    const int* __restrict__ node_ids) {
    int n = blockIdx.x;
    int tid = threadIdx.x;
    float val = tanhf(P[(size_t)n * HH + tid] + pb[tid]) * sw[tid];
    float s = blk_sum(val);
    if (tid == 0) {
        if (node_ids[n] != 0) {
            g_av[n] = s;
            atomicMax(&g_maxenc[2], enc_f(s));
        } else {
            g_av[n] = 0.f;
        }
    }
}

__global__ void pool_exp_kernel(const int* __restrict__ node_ids) {
    int i = blockIdx.x * blockDim.x + threadIdx.x;
    float e = 0.f;
    if (i < NN) {
        float smax = dec_f(g_maxenc[2]);
        if (node_ids[i] != 0) e = expf(g_av[i] - smax);
        g_bv[i] = e;
    }
    float r = blk_sum(e);
    if (threadIdx.x == 0) atomicAdd(&g_pool_sum, r);
}

#define FCHUNK 64
__global__ __launch_bounds__(HH) void final_kernel(const float* __restrict__ ns, float* __restrict__ out) {
    int base = blockIdx.x * FCHUNK;
    int tid = threadIdx.x;
    float sum = g_pool_sum;
    float inv = (sum > 0.f) ? 1.f / sum : 0.f;
    if (tid < FCHUNK) {
        int n = base + tid;
        if (n < NN) out[HH + n] = g_bv[n] * inv;
    }
    float acc = 0.f;
    for (int i = 0; i < FCHUNK; i++) {
        int n = base + i;
        if (n >= NN) break;
        float w = g_bv[n] * inv;
        acc = fmaf(w, ns[(size_t)n * HH + tid], acc);
    }
    atomicAdd(&out[tid], acc);
}

// ---------------- launcher ----------------
extern "C" void kernel_launch(void* const* d_in, const int* in_sizes, int n_in,
                              void* d_out, int out_size) {
    const int*   node_ids = (const int*)d_in[0];
    const int*   edge_index = (const int*)d_in[1];
    const float* emb    = (const float*)d_in[2];
    const float* proj_w = (const float*)d_in[3];
    const float* edge_w = (const float*)d_in[4];
    const float* ln_g   = (const float*)d_in[5];
    const float* ln_b   = (const float*)d_in[6];
    const float* pool_w = (const float*)d_in[7];
    const float* pool_b = (const float*)d_in[8];
    const float* score_w = (const float*)d_in[9];
    float* out = (float*)d_out;
    const int* src = edge_index;
    const int* dst = edge_index + EE;

    float *p_ns, *p_ns2, *p_h;
    cudaGetSymbolAddress((void**)&p_ns, g_ns);
    cudaGetSymbolAddress((void**)&p_ns2, g_ns2);
    cudaGetSymbolAddress((void**)&p_h, g_h);

    init_kernel<<<(NN + 255) / 256, 256>>>(out);
    deg_kernel<<<(EE + 255) / 256, 256>>>(dst);
    scan_kernel<<<1, 1024>>>();
    scatter_kernel<<<(EE + 255) / 256, 256>>>(src, dst);
    embed_kernel<<<NN, HH>>>(node_ids, emb);

    dim3 gemm_grid((NN + 127) / 128, 2);

    // layer 0
    sgemm_mma<<<gemm_grid, 256>>>(p_ns, proj_w, p_h, NN);
    ab_kernel<<<(NN * 32 + 255) / 256, 256>>>(p_h, edge_w);
    scores_kernel<<<(EE + 255) / 256, 256>>>(0);
    agg_kernel<<<NN, HH>>>(p_h, p_ns, p_ns2, ln_g, ln_b, 0);

    // layer 1
    sgemm_mma<<<gemm_grid, 256>>>(p_ns2, proj_w + HH * HH, p_h, NN);
    ab_kernel<<<(NN * 32 + 255) / 256, 256>>>(p_h, edge_w + 2 * HH);
    scores_kernel<<<(EE + 255) / 256, 256>>>(1);
    agg_kernel<<<NN, HH>>>(p_h, p_ns2, p_ns, ln_g + HH, ln_b + HH, 1);

    // pooling
    sgemm_mma<<<gemm_grid, 256>>>(p_ns, pool_w, p_h, NN);
    pool_s_kernel<<<NN, HH>>>(p_h, pool_b, score_w, node_ids);
    pool_exp_kernel<<<(NN + 255) / 256, 256>>>(node_ids);
    final_kernel<<<(NN + FCHUNK - 1) / FCHUNK, HH>>>(p_ns, out);
}

// round 6
// speedup vs baseline: 1.5001x; 1.0037x over previous
#include <cuda_runtime.h>
#include <cuda_bf16.h>
#include <math.h>
#include <stdint.h>

#define NN 20000
#define HH 256
#define EE 320000

// ---------------- scratch (device globals; no allocation allowed) ----------------
__device__ float g_ns[(size_t)NN * HH];
__device__ float g_ns2[(size_t)NN * HH];
__device__ float g_h[(size_t)NN * HH];
__device__ float g_av[NN];
__device__ float g_bv[NN];
__device__ int   g_deg[NN];
__device__ int   g_rowptr[NN + 1];
__device__ int   g_cursor[NN];
__device__ int   g_src_s[EE];
__device__ int   g_dst_s[EE];
__device__ float g_scores[EE];
__device__ unsigned g_maxenc[4];
__device__ float g_pool_sum;

// order-preserving float<->uint map for atomicMax on floats
__device__ __forceinline__ unsigned enc_f(float x) {
    unsigned u = __float_as_uint(x);
    return (u & 0x80000000u) ? ~u : (u | 0x80000000u);
}
__device__ __forceinline__ float dec_f(unsigned u) {
    return (u & 0x80000000u) ? __uint_as_float(u & 0x7fffffffu)
                             : __uint_as_float(~u);
}

__device__ __forceinline__ float blk_sum(float v) {
    __shared__ float sh[32];
    int lane = threadIdx.x & 31, w = threadIdx.x >> 5;
#pragma unroll
    for (int o = 16; o; o >>= 1) v += __shfl_down_sync(0xffffffffu, v, o);
    if (!lane) sh[w] = v;
    __syncthreads();
    int nw = blockDim.x >> 5;
    float r = (threadIdx.x < nw) ? sh[threadIdx.x] : 0.f;
    if (w == 0) {
#pragma unroll
        for (int o = 16; o; o >>= 1) r += __shfl_down_sync(0xffffffffu, r, o);
        if (!lane) sh[0] = r;
    }
    __syncthreads();
    r = sh[0];
    __syncthreads();
    return r;
}

// ---------------- setup kernels ----------------
__global__ void init_kernel(float* out) {
    int i = blockIdx.x * blockDim.x + threadIdx.x;
    if (i < NN) g_deg[i] = 0;
    if (blockIdx.x == 0) {
        if (threadIdx.x < 4) g_maxenc[threadIdx.x] = 0x007FFFFFu; // enc(-inf)
        if (threadIdx.x == 4) g_pool_sum = 0.f;
        if (threadIdx.x < HH) out[threadIdx.x] = 0.f;
    }
}

__global__ void deg_kernel(const int* __restrict__ dst) {
    int e = blockIdx.x * blockDim.x + threadIdx.x;
    if (e < EE) atomicAdd(&g_deg[dst[e]], 1);
}

__global__ void scan_kernel() {
    __shared__ int ssum[1024];
    const int CH = (NN + 1023) / 1024; // 20
    int tid = threadIdx.x;
    int start = tid * CH;
    int local[32];
    int s = 0;
#pragma unroll
    for (int i = 0; i < CH; i++) {
        int idx = start + i;
        int d = (idx < NN) ? g_deg[idx] : 0;
        local[i] = s;
        s += d;
    }
    ssum[tid] = s;
    __syncthreads();
    for (int off = 1; off < 1024; off <<= 1) {
        int v = 0;
        if (tid >= off) v = ssum[tid - off];
        __syncthreads();
        if (tid >= off) ssum[tid] += v;
        __syncthreads();
    }
    int prefix = ssum[tid] - s;
#pragma unroll
    for (int i = 0; i < CH; i++) {
        int idx = start + i;
        if (idx < NN) {
            int p = prefix + local[i];
            g_rowptr[idx] = p;
            g_cursor[idx] = p;
        }
    }
    if (tid == 1023) g_rowptr[NN] = ssum[1023];
}

__global__ void scatter_kernel(const int* __restrict__ src, const int* __restrict__ dst) {
    int e = blockIdx.x * blockDim.x + threadIdx.x;
    if (e < EE) {
        int d = dst[e];
        int pos = atomicAdd(&g_cursor[d], 1);
        g_src_s[pos] = src[e];
        g_dst_s[pos] = d;
    }
}

__global__ void embed_kernel(const int* __restrict__ node_ids, const float* __restrict__ emb) {
    int n = blockIdx.x;
    int t = threadIdx.x;
    g_ns[(size_t)n * HH + t] = emb[(size_t)node_ids[n] * HH + t];
}

// ---------------- TF32 mma.sync SGEMM: C[M,256] = A[M,256] * B[256,256]^T ----------------
#define SPAD 20  // smem row stride in floats -> conflict-free fragment loads

__device__ __forceinline__ uint32_t f2tf32(float f) {
    uint32_t r;
    asm("cvt.rna.tf32.f32 %0, %1;" : "=r"(r) : "f"(f));
    return r;
}

__device__ __forceinline__ void mma_tf32(float* c, const uint32_t* a, const uint32_t* b) {
    asm volatile(
        "mma.sync.aligned.m16n8k8.row.col.f32.tf32.tf32.f32 "
        "{%0,%1,%2,%3}, {%4,%5,%6,%7}, {%8,%9}, {%0,%1,%2,%3};"
        : "+f"(c[0]), "+f"(c[1]), "+f"(c[2]), "+f"(c[3])
        : "r"(a[0]), "r"(a[1]), "r"(a[2]), "r"(a[3]), "r"(b[0]), "r"(b[1]));
}

__global__ __launch_bounds__(256) void sgemm_mma(const float* __restrict__ A,
                                                 const float* __restrict__ B,
                                                 float* __restrict__ C, int M) {
    __shared__ uint32_t As[128 * SPAD];
    __shared__ uint32_t Bs[128 * SPAD];
    int tid = threadIdx.x;
    int lane = tid & 31, w = tid >> 5;
    int wm = w & 1, wn = w >> 1;           // warp grid 2 (m) x 4 (n)
    int g = lane >> 2, t4 = lane & 3;      // group-id, thread-in-group
    int bm = blockIdx.x * 128, bn = blockIdx.y * 128;

    float c[4][4][4];
#pragma unroll
    for (int mi = 0; mi < 4; mi++)
#pragma unroll
        for (int ni = 0; ni < 4; ni++)
#pragma unroll
            for (int j = 0; j < 4; j++) c[mi][ni][j] = 0.f;

    int s0 = tid, s1 = tid + 256;
    int r0 = s0 >> 2, q0 = s0 & 3;
    int r1 = s1 >> 2, q1 = s1 & 3;
    int ga0 = bm + r0, ga1 = bm + r1;

    float4 ra0, ra1, rb0, rb1;
    const float4 z4 = make_float4(0.f, 0.f, 0.f, 0.f);

    {
        ra0 = (ga0 < M) ? *(const float4*)&A[(size_t)ga0 * HH + q0 * 4] : z4;
        ra1 = (ga1 < M) ? *(const float4*)&A[(size_t)ga1 * HH + q1 * 4] : z4;
        rb0 = *(const float4*)&B[(size_t)(bn + r0) * HH + q0 * 4];
        rb1 = *(const float4*)&B[(size_t)(bn + r1) * HH + q1 * 4];
    }

#pragma unroll 1
    for (int it = 0; it < 16; it++) {
        {
            uint32_t* pa0 = &As[r0 * SPAD + q0 * 4];
            pa0[0] = f2tf32(ra0.x); pa0[1] = f2tf32(ra0.y); pa0[2] = f2tf32(ra0.z); pa0[3] = f2tf32(ra0.w);
            uint32_t* pa1 = &As[r1 * SPAD + q1 * 4];
            pa1[0] = f2tf32(ra1.x); pa1[1] = f2tf32(ra1.y); pa1[2] = f2tf32(ra1.z); pa1[3] = f2tf32(ra1.w);
            uint32_t* pb0 = &Bs[r0 * SPAD + q0 * 4];
            pb0[0] = f2tf32(rb0.x); pb0[1] = f2tf32(rb0.y); pb0[2] = f2tf32(rb0.z); pb0[3] = f2tf32(rb0.w);
            uint32_t* pb1 = &Bs[r1 * SPAD + q1 * 4];
            pb1[0] = f2tf32(rb1.x); pb1[1] = f2tf32(rb1.y); pb1[2] = f2tf32(rb1.z); pb1[3] = f2tf32(rb1.w);
        }
        __syncthreads();

        if (it < 15) {
            int k0 = (it + 1) * 16;
            ra0 = (ga0 < M) ? *(const float4*)&A[(size_t)ga0 * HH + k0 + q0 * 4] : z4;
            ra1 = (ga1 < M) ? *(const float4*)&A[(size_t)ga1 * HH + k0 + q1 * 4] : z4;
            rb0 = *(const float4*)&B[(size_t)(bn + r0) * HH + k0 + q0 * 4];
            rb1 = *(const float4*)&B[(size_t)(bn + r1) * HH + k0 + q1 * 4];
        }

#pragma unroll
        for (int ks = 0; ks < 2; ks++) {
            int kb = ks * 8 + t4;
            uint32_t af[4][4];
#pragma unroll
            for (int mi = 0; mi < 4; mi++) {
                int rr = wm * 64 + mi * 16 + g;
                af[mi][0] = As[rr * SPAD + kb];
                af[mi][1] = As[(rr + 8) * SPAD + kb];
                af[mi][2] = As[rr * SPAD + kb + 4];
                af[mi][3] = As[(rr + 8) * SPAD + kb + 4];
            }
            uint32_t bf[4][2];
#pragma unroll
            for (int ni = 0; ni < 4; ni++) {
                int cc = wn * 32 + ni * 8 + g;
                bf[ni][0] = Bs[cc * SPAD + kb];
                bf[ni][1] = Bs[cc * SPAD + kb + 4];
            }
#pragma unroll
            for (int mi = 0; mi < 4; mi++)
#pragma unroll
                for (int ni = 0; ni < 4; ni++)
                    mma_tf32(c[mi][ni], af[mi], bf[ni]);
        }
        __syncthreads();
    }

#pragma unroll
    for (int mi = 0; mi < 4; mi++) {
#pragma unroll
        for (int ni = 0; ni < 4; ni++) {
            int row = bm + wm * 64 + mi * 16 + g;
            int col = bn + wn * 32 + ni * 8 + 2 * t4;
            if (row < M)
                *(float2*)&C[(size_t)row * HH + col] = make_float2(c[mi][ni][0], c[mi][ni][1]);
            if (row + 8 < M)
                *(float2*)&C[(size_t)(row + 8) * HH + col] = make_float2(c[mi][ni][2], c[mi][ni][3]);
        }
    }
}

// ---------------- per-layer kernels ----------------
__global__ void ab_kernel(const float* __restrict__ hbuf, const float* __restrict__ ew) {
    int wg = (blockIdx.x * blockDim.x + threadIdx.x) >> 5;
    int lane = threadIdx.x & 31;
    if (wg >= NN) return;
    const float* row = hbuf + (size_t)wg * HH;
    float a = 0.f, b = 0.f;
#pragma unroll
    for (int k = lane; k < HH; k += 32) {
        float hv = row[k];
        a = fmaf(hv, ew[k], a);
        b = fmaf(hv, ew[HH + k], b);
    }
#pragma unroll
    for (int o = 16; o; o >>= 1) {
        a += __shfl_down_sync(0xffffffffu, a, o);
        b += __shfl_down_sync(0xffffffffu, b, o);
    }
    if (!lane) { g_av[wg] = a; g_bv[wg] = b; }
}

__global__ void scores_kernel(int slot) {
    __shared__ float sh[32];
    int i = blockIdx.x * blockDim.x + threadIdx.x;
    float s = -3.4e38f;
    if (i < EE) {
        float v = g_av[g_src_s[i]] + g_bv[g_dst_s[i]];
        v = (v >= 0.f) ? v : 0.2f * v;
        g_scores[i] = v;
        s = v;
    }
    int lane = threadIdx.x & 31, w = threadIdx.x >> 5;
#pragma unroll
    for (int o = 16; o; o >>= 1) s = fmaxf(s, __shfl_down_sync(0xffffffffu, s, o));
    if (!lane) sh[w] = s;
    __syncthreads();
    if (threadIdx.x == 0) {
        float m = sh[0];
        for (int k = 1; k < (int)(blockDim.x >> 5); k++) m = fmaxf(m, sh[k]);
        atomicMax(&g_maxenc[slot], enc_f(m));
    }
}

// fused: denom -> smem-staged weighted gather -> residual -> LayerNorm -> GELU
__global__ __launch_bounds__(HH) void agg_kernel(const float* __restrict__ hbuf,
                                                 const float* __restrict__ nsin,
                                                 float* __restrict__ nsout,
                                                 const float* __restrict__ gamma,
                                                 const float* __restrict__ beta,
                                                 int slot) {
    __shared__ int   sh_src[HH];
    __shared__ float sh_w[HH];
    int n = blockIdx.x;
    int tid = threadIdx.x;
    int beg = g_rowptr[n], end = g_rowptr[n + 1];
    float smax = dec_f(g_maxenc[slot]);

    // pass 1: denom (parallel over edges)
    float local = 0.f;
    for (int i = beg + tid; i < end; i += HH)
        local += expf(g_scores[i] - smax);
    float denom = blk_sum(local) + 1e-6f;
    float inv = 1.f / denom;

    // pass 2: stage (src, weight) in smem, then MLP-rich gather
    float acc0 = 0.f, acc1 = 0.f, acc2 = 0.f, acc3 = 0.f;
    for (int cs = beg; cs < end; cs += HH) {
        int cnt = min(HH, end - cs);
        __syncthreads();
        if (tid < cnt) {
            sh_src[tid] = g_src_s[cs + tid];
            sh_w[tid] = expf(g_scores[cs + tid] - smax) * inv;
        }
        __syncthreads();
        int j = 0;
        for (; j + 4 <= cnt; j += 4) {
            int   s0 = sh_src[j],     s1 = sh_src[j + 1], s2 = sh_src[j + 2], s3 = sh_src[j + 3];
            float w0 = sh_w[j],       w1 = sh_w[j + 1],   w2 = sh_w[j + 2],   w3 = sh_w[j + 3];
            float h0 = hbuf[(size_t)s0 * HH + tid];
            float h1 = hbuf[(size_t)s1 * HH + tid];
            float h2 = hbuf[(size_t)s2 * HH + tid];
            float h3 = hbuf[(size_t)s3 * HH + tid];
            acc0 = fmaf(h0, w0, acc0);
            acc1 = fmaf(h1, w1, acc1);
            acc2 = fmaf(h2, w2, acc2);
            acc3 = fmaf(h3, w3, acc3);
        }
        for (; j < cnt; j++)
            acc0 = fmaf(hbuf[(size_t)sh_src[j] * HH + tid], sh_w[j], acc0);
    }
    float x = ((acc0 + acc1) + (acc2 + acc3)) + nsin[(size_t)n * HH + tid];
    float m = blk_sum(x) * (1.f / HH);
    float d = x - m;
    float var = blk_sum(d * d) * (1.f / HH);
    float y = d * rsqrtf(var + 1e-5f) * gamma[tid] + beta[tid];
    float out = 0.5f * y * (1.f + erff(y * 0.70710678118654752440f));
    nsout[(size_t)n * HH + tid] = out;
}

// ---------------- pooling ----------------
__global__ __launch_bounds__(HH) void pool_s_kernel(const float* __restrict__ P,
                                                    const float* __restrict__ pb,
                                                    const float* __restrict__ sw,
                                                    const int* __restrict__ node_ids) {
    int n = blockIdx.x;
    int tid = threadIdx.x;
    float val = tanhf(P[(size_t)n * HH + tid] + pb[tid]) * sw[tid];
    float s = blk_sum(val);
    if (tid == 0) {
        if (node_ids[n] != 0) {
            g_av[n] = s;
            atomicMax(&g_maxenc[2], enc_f(s));
        } else {
            g_av[n] = 0.f;
        }
    }
}

__global__ void pool_exp_kernel(const int* __restrict__ node_ids) {
    int i = blockIdx.x * blockDim.x + threadIdx.x;
    float e = 0.f;
    if (i < NN) {
        float smax = dec_f(g_maxenc[2]);
        if (node_ids[i] != 0) e = expf(g_av[i] - smax);
        g_bv[i] = e;
    }
    float r = blk_sum(e);
    if (threadIdx.x == 0) atomicAdd(&g_pool_sum, r);
}

#define FCHUNK 64
__global__ __launch_bounds__(HH) void final_kernel(const float* __restrict__ ns, float* __restrict__ out) {
    int base = blockIdx.x * FCHUNK;
    int tid = threadIdx.x;
    float sum = g_pool_sum;
    float inv = (sum > 0.f) ? 1.f / sum : 0.f;
    if (tid < FCHUNK) {
        int n = base + tid;
        if (n < NN) out[HH + n] = g_bv[n] * inv;
    }
    int lim = min(FCHUNK, NN - base);
    float a0 = 0.f, a1 = 0.f, a2 = 0.f, a3 = 0.f;
    int i = 0;
    for (; i + 4 <= lim; i += 4) {
        float w0 = g_bv[base + i] * inv,     w1 = g_bv[base + i + 1] * inv;
        float w2 = g_bv[base + i + 2] * inv, w3 = g_bv[base + i + 3] * inv;
        float h0 = ns[(size_t)(base + i) * HH + tid];
        float h1 = ns[(size_t)(base + i + 1) * HH + tid];
        float h2 = ns[(size_t)(base + i + 2) * HH + tid];
        float h3 = ns[(size_t)(base + i + 3) * HH + tid];
        a0 = fmaf(w0, h0, a0); a1 = fmaf(w1, h1, a1);
        a2 = fmaf(w2, h2, a2); a3 = fmaf(w3, h3, a3);
    }
    for (; i < lim; i++)
        a0 = fmaf(g_bv[base + i] * inv, ns[(size_t)(base + i) * HH + tid], a0);
    atomicAdd(&out[tid], (a0 + a1) + (a2 + a3));
}

// ---------------- launcher ----------------
extern "C" void kernel_launch(void* const* d_in, const int* in_sizes, int n_in,
                              void* d_out, int out_size) {
    const int*   node_ids = (const int*)d_in[0];
    const int*   edge_index = (const int*)d_in[1];
    const float* emb    = (const float*)d_in[2];
    const float* proj_w = (const float*)d_in[3];
    const float* edge_w = (const float*)d_in[4];
    const float* ln_g   = (const float*)d_in[5];
    const float* ln_b   = (const float*)d_in[6];
    const float* pool_w = (const float*)d_in[7];
    const float* pool_b = (const float*)d_in[8];
    const float* score_w = (const float*)d_in[9];
    float* out = (float*)d_out;
    const int* src = edge_index;
    const int* dst = edge_index + EE;

    float *p_ns, *p_ns2, *p_h;
    cudaGetSymbolAddress((void**)&p_ns, g_ns);
    cudaGetSymbolAddress((void**)&p_ns2, g_ns2);
    cudaGetSymbolAddress((void**)&p_h, g_h);

    init_kernel<<<(NN + 255) / 256, 256>>>(out);
    deg_kernel<<<(EE + 255) / 256, 256>>>(dst);
    scan_kernel<<<1, 1024>>>();
    scatter_kernel<<<(EE + 255) / 256, 256>>>(src, dst);
    embed_kernel<<<NN, HH>>>(node_ids, emb);

    dim3 gemm_grid((NN + 127) / 128, 2);

    // layer 0
    sgemm_mma<<<gemm_grid, 256>>>(p_ns, proj_w, p_h, NN);
    ab_kernel<<<(NN * 32 + 255) / 256, 256>>>(p_h, edge_w);
    scores_kernel<<<(EE + 255) / 256, 256>>>(0);
    agg_kernel<<<NN, HH>>>(p_h, p_ns, p_ns2, ln_g, ln_b, 0);

    // layer 1
    sgemm_mma<<<gemm_grid, 256>>>(p_ns2, proj_w + HH * HH, p_h, NN);
    ab_kernel<<<(NN * 32 + 255) / 256, 256>>>(p_h, edge_w + 2 * HH);
    scores_kernel<<<(EE + 255) / 256, 256>>>(1);
    agg_kernel<<<NN, HH>>>(p_h, p_ns2, p_ns, ln_g + HH, ln_b + HH, 1);

    // pooling
    sgemm_mma<<<gemm_grid, 256>>>(p_ns, pool_w, p_h, NN);
    pool_s_kernel<<<NN, HH>>>(p_h, pool_b, score_w, node_ids);
    pool_exp_kernel<<<(NN + 255) / 256, 256>>>(node_ids);
    final_kernel<<<(NN + FCHUNK - 1) / FCHUNK, HH>>>(p_ns, out);
}

// round 7
// speedup vs baseline: 2.0877x; 1.3917x over previous
#include <cuda_runtime.h>
#include <cuda_bf16.h>
#include <math.h>
#include <stdint.h>

#define NN 20000
#define HH 256
#define EE 320000

// ---------------- scratch (device globals; no allocation allowed) ----------------
__device__ float g_ns[(size_t)NN * HH];
__device__ float g_ns2[(size_t)NN * HH];
__device__ float g_h[(size_t)NN * HH];
__device__ float g_av[NN];
__device__ float g_bv[NN];
__device__ int   g_deg[NN];
__device__ int   g_rowptr[NN + 1];
__device__ int   g_cursor[NN];
__device__ int   g_src_s[EE];
__device__ unsigned g_maxenc[4];
__device__ float g_pool_sum;

// order-preserving float<->uint map for atomicMax on floats
__device__ __forceinline__ unsigned enc_f(float x) {
    unsigned u = __float_as_uint(x);
    return (u & 0x80000000u) ? ~u : (u | 0x80000000u);
}
__device__ __forceinline__ float dec_f(unsigned u) {
    return (u & 0x80000000u) ? __uint_as_float(u & 0x7fffffffu)
                             : __uint_as_float(~u);
}

__device__ __forceinline__ float blk_sum(float v) {
    __shared__ float sh[32];
    int lane = threadIdx.x & 31, w = threadIdx.x >> 5;
#pragma unroll
    for (int o = 16; o; o >>= 1) v += __shfl_down_sync(0xffffffffu, v, o);
    if (!lane) sh[w] = v;
    __syncthreads();
    int nw = blockDim.x >> 5;
    float r = (threadIdx.x < nw) ? sh[threadIdx.x] : 0.f;
    if (w == 0) {
#pragma unroll
        for (int o = 16; o; o >>= 1) r += __shfl_down_sync(0xffffffffu, r, o);
        if (!lane) sh[0] = r;
    }
    __syncthreads();
    r = sh[0];
    __syncthreads();
    return r;
}

__device__ __forceinline__ float warp_sum(float v) {
#pragma unroll
    for (int o = 16; o; o >>= 1) v += __shfl_xor_sync(0xffffffffu, v, o);
    return v;
}

// ---------------- setup kernels ----------------
__global__ void init_kernel(float* out) {
    int i = blockIdx.x * blockDim.x + threadIdx.x;
    if (i < NN) g_deg[i] = 0;
    if (blockIdx.x == 0) {
        if (threadIdx.x < 4) g_maxenc[threadIdx.x] = 0x007FFFFFu; // enc(-inf)
        if (threadIdx.x == 4) g_pool_sum = 0.f;
        if (threadIdx.x < HH) out[threadIdx.x] = 0.f;
    }
}

__global__ void deg_kernel(const int* __restrict__ dst) {
    int e = blockIdx.x * blockDim.x + threadIdx.x;
    if (e < EE) atomicAdd(&g_deg[dst[e]], 1);
}

__global__ void scan_kernel() {
    __shared__ int ssum[1024];
    const int CH = (NN + 1023) / 1024; // 20
    int tid = threadIdx.x;
    int start = tid * CH;
    int local[32];
    int s = 0;
#pragma unroll
    for (int i = 0; i < CH; i++) {
        int idx = start + i;
        int d = (idx < NN) ? g_deg[idx] : 0;
        local[i] = s;
        s += d;
    }
    ssum[tid] = s;
    __syncthreads();
    for (int off = 1; off < 1024; off <<= 1) {
        int v = 0;
        if (tid >= off) v = ssum[tid - off];
        __syncthreads();
        if (tid >= off) ssum[tid] += v;
        __syncthreads();
    }
    int prefix = ssum[tid] - s;
#pragma unroll
    for (int i = 0; i < CH; i++) {
        int idx = start + i;
        if (idx < NN) {
            int p = prefix + local[i];
            g_rowptr[idx] = p;
            g_cursor[idx] = p;
        }
    }
    if (tid == 1023) g_rowptr[NN] = ssum[1023];
}

__global__ void scatter_kernel(const int* __restrict__ src, const int* __restrict__ dst) {
    int e = blockIdx.x * blockDim.x + threadIdx.x;
    if (e < EE) {
        int d = dst[e];
        int pos = atomicAdd(&g_cursor[d], 1);
        g_src_s[pos] = src[e];
    }
}

__global__ void embed_kernel(const int* __restrict__ node_ids, const float* __restrict__ emb) {
    int n = blockIdx.x;
    int t = threadIdx.x;
    g_ns[(size_t)n * HH + t] = emb[(size_t)node_ids[n] * HH + t];
}

// ---------------- TF32 mma.sync SGEMM: C[M,256] = A[M,256] * B[256,256]^T ----------------
#define SPAD 20  // smem row stride in floats -> conflict-free fragment loads

__device__ __forceinline__ uint32_t f2tf32(float f) {
    uint32_t r;
    asm("cvt.rna.tf32.f32 %0, %1;" : "=r"(r) : "f"(f));
    return r;
}

__device__ __forceinline__ void mma_tf32(float* c, const uint32_t* a, const uint32_t* b) {
    asm volatile(
        "mma.sync.aligned.m16n8k8.row.col.f32.tf32.tf32.f32 "
        "{%0,%1,%2,%3}, {%4,%5,%6,%7}, {%8,%9}, {%0,%1,%2,%3};"
        : "+f"(c[0]), "+f"(c[1]), "+f"(c[2]), "+f"(c[3])
        : "r"(a[0]), "r"(a[1]), "r"(a[2]), "r"(a[3]), "r"(b[0]), "r"(b[1]));
}

__global__ __launch_bounds__(256) void sgemm_mma(const float* __restrict__ A,
                                                 const float* __restrict__ B,
                                                 float* __restrict__ C, int M) {
    __shared__ uint32_t As[128 * SPAD];
    __shared__ uint32_t Bs[128 * SPAD];
    int tid = threadIdx.x;
    int lane = tid & 31, w = tid >> 5;
    int wm = w & 1, wn = w >> 1;           // warp grid 2 (m) x 4 (n)
    int g = lane >> 2, t4 = lane & 3;      // group-id, thread-in-group
    int bm = blockIdx.x * 128, bn = blockIdx.y * 128;

    float c[4][4][4];
#pragma unroll
    for (int mi = 0; mi < 4; mi++)
#pragma unroll
        for (int ni = 0; ni < 4; ni++)
#pragma unroll
            for (int j = 0; j < 4; j++) c[mi][ni][j] = 0.f;

    int s0 = tid, s1 = tid + 256;
    int r0 = s0 >> 2, q0 = s0 & 3;
    int r1 = s1 >> 2, q1 = s1 & 3;
    int ga0 = bm + r0, ga1 = bm + r1;

    float4 ra0, ra1, rb0, rb1;
    const float4 z4 = make_float4(0.f, 0.f, 0.f, 0.f);

    {
        ra0 = (ga0 < M) ? *(const float4*)&A[(size_t)ga0 * HH + q0 * 4] : z4;
        ra1 = (ga1 < M) ? *(const float4*)&A[(size_t)ga1 * HH + q1 * 4] : z4;
        rb0 = *(const float4*)&B[(size_t)(bn + r0) * HH + q0 * 4];
        rb1 = *(const float4*)&B[(size_t)(bn + r1) * HH + q1 * 4];
    }

#pragma unroll 1
    for (int it = 0; it < 16; it++) {
        {
            uint32_t* pa0 = &As[r0 * SPAD + q0 * 4];
            pa0[0] = f2tf32(ra0.x); pa0[1] = f2tf32(ra0.y); pa0[2] = f2tf32(ra0.z); pa0[3] = f2tf32(ra0.w);
            uint32_t* pa1 = &As[r1 * SPAD + q1 * 4];
            pa1[0] = f2tf32(ra1.x); pa1[1] = f2tf32(ra1.y); pa1[2] = f2tf32(ra1.z); pa1[3] = f2tf32(ra1.w);
            uint32_t* pb0 = &Bs[r0 * SPAD + q0 * 4];
            pb0[0] = f2tf32(rb0.x); pb0[1] = f2tf32(rb0.y); pb0[2] = f2tf32(rb0.z); pb0[3] = f2tf32(rb0.w);
            uint32_t* pb1 = &Bs[r1 * SPAD + q1 * 4];
            pb1[0] = f2tf32(rb1.x); pb1[1] = f2tf32(rb1.y); pb1[2] = f2tf32(rb1.z); pb1[3] = f2tf32(rb1.w);
        }
        __syncthreads();

        if (it < 15) {
            int k0 = (it + 1) * 16;
            ra0 = (ga0 < M) ? *(const float4*)&A[(size_t)ga0 * HH + k0 + q0 * 4] : z4;
            ra1 = (ga1 < M) ? *(const float4*)&A[(size_t)ga1 * HH + k0 + q1 * 4] : z4;
            rb0 = *(const float4*)&B[(size_t)(bn + r0) * HH + k0 + q0 * 4];
            rb1 = *(const float4*)&B[(size_t)(bn + r1) * HH + k0 + q1 * 4];
        }

#pragma unroll
        for (int ks = 0; ks < 2; ks++) {
            int kb = ks * 8 + t4;
            uint32_t af[4][4];
#pragma unroll
            for (int mi = 0; mi < 4; mi++) {
                int rr = wm * 64 + mi * 16 + g;
                af[mi][0] = As[rr * SPAD + kb];
                af[mi][1] = As[(rr + 8) * SPAD + kb];
                af[mi][2] = As[rr * SPAD + kb + 4];
                af[mi][3] = As[(rr + 8) * SPAD + kb + 4];
            }
            uint32_t bf[4][2];
#pragma unroll
            for (int ni = 0; ni < 4; ni++) {
                int cc = wn * 32 + ni * 8 + g;
                bf[ni][0] = Bs[cc * SPAD + kb];
                bf[ni][1] = Bs[cc * SPAD + kb + 4];
            }
#pragma unroll
            for (int mi = 0; mi < 4; mi++)
#pragma unroll
                for (int ni = 0; ni < 4; ni++)
                    mma_tf32(c[mi][ni], af[mi], bf[ni]);
        }
        __syncthreads();
    }

#pragma unroll
    for (int mi = 0; mi < 4; mi++) {
#pragma unroll
        for (int ni = 0; ni < 4; ni++) {
            int row = bm + wm * 64 + mi * 16 + g;
            int col = bn + wn * 32 + ni * 8 + 2 * t4;
            if (row < M)
                *(float2*)&C[(size_t)row * HH + col] = make_float2(c[mi][ni][0], c[mi][ni][1]);
            if (row + 8 < M)
                *(float2*)&C[(size_t)(row + 8) * HH + col] = make_float2(c[mi][ni][2], c[mi][ni][3]);
        }
    }
}

// ---------------- per-layer kernels ----------------
__global__ void ab_kernel(const float* __restrict__ hbuf, const float* __restrict__ ew) {
    int wg = (blockIdx.x * blockDim.x + threadIdx.x) >> 5;
    int lane = threadIdx.x & 31;
    if (wg >= NN) return;
    const float* row = hbuf + (size_t)wg * HH;
    float a = 0.f, b = 0.f;
#pragma unroll
    for (int k = lane; k < HH; k += 32) {
        float hv = row[k];
        a = fmaf(hv, ew[k], a);
        b = fmaf(hv, ew[HH + k], b);
    }
#pragma unroll
    for (int o = 16; o; o >>= 1) {
        a += __shfl_down_sync(0xffffffffu, a, o);
        b += __shfl_down_sync(0xffffffffu, b, o);
    }
    if (!lane) { g_av[wg] = a; g_bv[wg] = b; }
}

// warp-per-node fused aggregation: inline softmax weights (no global max; the
// global max cancels in w = exp(s-max)/sum exp(s-max) up to the +1e-6 term,
// a ~1e-7 relative perturbation), weighted gather-sum, residual, LN, GELU.
__global__ __launch_bounds__(256) void agg_kernel(const float* __restrict__ hbuf,
                                                  const float* __restrict__ nsin,
                                                  float* __restrict__ nsout,
                                                  const float* __restrict__ gamma,
                                                  const float* __restrict__ beta) {
    int wid = threadIdx.x >> 5, lane = threadIdx.x & 31;
    int n = blockIdx.x * 8 + wid;
    if (n >= NN) return;
    int beg = g_rowptr[n], end = g_rowptr[n + 1];
    float bvn = g_bv[n];

    float4 acc0 = make_float4(0.f, 0.f, 0.f, 0.f);
    float4 acc1 = make_float4(0.f, 0.f, 0.f, 0.f);
    float wlocal = 0.f;

    for (int base = beg; base < end; base += 32) {
        int cnt = min(32, end - base);
        int sv = 0;
        float wv = 0.f;
        if (lane < cnt) {
            sv = g_src_s[base + lane];
            float sc = g_av[sv] + bvn;
            sc = (sc >= 0.f) ? sc : 0.2f * sc;
            wv = expf(sc);
        }
        wlocal += wv;
        int j = 0;
        for (; j + 2 <= cnt; j += 2) {
            int   sj0 = __shfl_sync(0xffffffffu, sv, j);
            int   sj1 = __shfl_sync(0xffffffffu, sv, j + 1);
            float wj0 = __shfl_sync(0xffffffffu, wv, j);
            float wj1 = __shfl_sync(0xffffffffu, wv, j + 1);
            const float4* ra = (const float4*)&hbuf[(size_t)sj0 * HH];
            const float4* rb = (const float4*)&hbuf[(size_t)sj1 * HH];
            float4 a0 = ra[lane], a1 = ra[32 + lane];
            float4 b0 = rb[lane], b1 = rb[32 + lane];
            acc0.x = fmaf(a0.x, wj0, acc0.x); acc0.y = fmaf(a0.y, wj0, acc0.y);
            acc0.z = fmaf(a0.z, wj0, acc0.z); acc0.w = fmaf(a0.w, wj0, acc0.w);
            acc1.x = fmaf(a1.x, wj0, acc1.x); acc1.y = fmaf(a1.y, wj0, acc1.y);
            acc1.z = fmaf(a1.z, wj0, acc1.z); acc1.w = fmaf(a1.w, wj0, acc1.w);
            acc0.x = fmaf(b0.x, wj1, acc0.x); acc0.y = fmaf(b0.y, wj1, acc0.y);
            acc0.z = fmaf(b0.z, wj1, acc0.z); acc0.w = fmaf(b0.w, wj1, acc0.w);
            acc1.x = fmaf(b1.x, wj1, acc1.x); acc1.y = fmaf(b1.y, wj1, acc1.y);
            acc1.z = fmaf(b1.z, wj1, acc1.z); acc1.w = fmaf(b1.w, wj1, acc1.w);
        }
        if (j < cnt) {
            int   sj = __shfl_sync(0xffffffffu, sv, j);
            float wj = __shfl_sync(0xffffffffu, wv, j);
            const float4* ra = (const float4*)&hbuf[(size_t)sj * HH];
            float4 a0 = ra[lane], a1 = ra[32 + lane];
            acc0.x = fmaf(a0.x, wj, acc0.x); acc0.y = fmaf(a0.y, wj, acc0.y);
            acc0.z = fmaf(a0.z, wj, acc0.z); acc0.w = fmaf(a0.w, wj, acc0.w);
            acc1.x = fmaf(a1.x, wj, acc1.x); acc1.y = fmaf(a1.y, wj, acc1.y);
            acc1.z = fmaf(a1.z, wj, acc1.z); acc1.w = fmaf(a1.w, wj, acc1.w);
        }
    }
    float denom = warp_sum(wlocal) + 1e-6f;
    float inv = 1.f / denom;

    const float4* ns4 = (const float4*)&nsin[(size_t)n * HH];
    float4 r0 = ns4[lane], r1 = ns4[32 + lane];
    float x[8];
    x[0] = fmaf(acc0.x, inv, r0.x); x[1] = fmaf(acc0.y, inv, r0.y);
    x[2] = fmaf(acc0.z, inv, r0.z); x[3] = fmaf(acc0.w, inv, r0.w);
    x[4] = fmaf(acc1.x, inv, r1.x); x[5] = fmaf(acc1.y, inv, r1.y);
    x[6] = fmaf(acc1.z, inv, r1.z); x[7] = fmaf(acc1.w, inv, r1.w);

    float lsum = ((x[0] + x[1]) + (x[2] + x[3])) + ((x[4] + x[5]) + (x[6] + x[7]));
    float m = warp_sum(lsum) * (1.f / HH);
    float vsum = 0.f;
#pragma unroll
    for (int i = 0; i < 8; i++) {
        float d = x[i] - m;
        vsum = fmaf(d, d, vsum);
    }
    float var = warp_sum(vsum) * (1.f / HH);
    float rs = rsqrtf(var + 1e-5f);

    const float4* gg = (const float4*)&gamma[0];
    const float4* bb = (const float4*)&beta[0];
    float4 g0 = gg[lane], g1 = gg[32 + lane];
    float4 b0 = bb[lane], b1 = bb[32 + lane];
    float gam[8] = {g0.x, g0.y, g0.z, g0.w, g1.x, g1.y, g1.z, g1.w};
    float bet[8] = {b0.x, b0.y, b0.z, b0.w, b1.x, b1.y, b1.z, b1.w};
    float o[8];
#pragma unroll
    for (int i = 0; i < 8; i++) {
        float y = fmaf((x[i] - m) * rs, gam[i], bet[i]);
        o[i] = 0.5f * y * (1.f + erff(y * 0.70710678118654752440f));
    }
    float4* out4 = (float4*)&nsout[(size_t)n * HH];
    out4[lane] = make_float4(o[0], o[1], o[2], o[3]);
    out4[32 + lane] = make_float4(o[4], o[5], o[6], o[7]);
}

// ---------------- pooling ----------------
// warp-per-node: s[n] = sum(tanh(P[n]+pb) * sw)
__global__ __launch_bounds__(256) void pool_s_kernel(const float* __restrict__ P,
                                                     const float* __restrict__ pb,
                                                     const float* __restrict__ sw,
                                                     const int* __restrict__ node_ids) {
    int wid = threadIdx.x >> 5, lane = threadIdx.x & 31;
    int n = blockIdx.x * 8 + wid;
    if (n >= NN) return;
    const float4* P4 = (const float4*)&P[(size_t)n * HH];
    const float4* pb4 = (const float4*)&pb[0];
    const float4* sw4 = (const float4*)&sw[0];
    float4 p0 = P4[lane], p1 = P4[32 + lane];
    float4 c0 = pb4[lane], c1 = pb4[32 + lane];
    float4 w0 = sw4[lane], w1 = sw4[32 + lane];
    float v = tanhf(p0.x + c0.x) * w0.x + tanhf(p0.y + c0.y) * w0.y +
              tanhf(p0.z + c0.z) * w0.z + tanhf(p0.w + c0.w) * w0.w +
              tanhf(p1.x + c1.x) * w1.x + tanhf(p1.y + c1.y) * w1.y +
              tanhf(p1.z + c1.z) * w1.z + tanhf(p1.w + c1.w) * w1.w;
    float s = warp_sum(v);
    if (!lane) {
        if (node_ids[n] != 0) {
            g_av[n] = s;
            atomicMax(&g_maxenc[0], enc_f(s));
        } else {
            g_av[n] = 0.f;
        }
    }
}

__global__ void pool_exp_kernel(const int* __restrict__ node_ids) {
    int i = blockIdx.x * blockDim.x + threadIdx.x;
    float e = 0.f;
    if (i < NN) {
        float smax = dec_f(g_maxenc[0]);
        if (node_ids[i] != 0) e = expf(g_av[i] - smax);
        g_bv[i] = e;
    }
    float r = blk_sum(e);
    if (threadIdx.x == 0) atomicAdd(&g_pool_sum, r);
}

#define FCHUNK 64
__global__ __launch_bounds__(HH) void final_kernel(const float* __restrict__ ns, float* __restrict__ out) {
    int base = blockIdx.x * FCHUNK;
    int tid = threadIdx.x;
    float sum = g_pool_sum;
    float inv = (sum > 0.f) ? 1.f / sum : 0.f;
    if (tid < FCHUNK) {
        int n = base + tid;
        if (n < NN) out[HH + n] = g_bv[n] * inv;
    }
    int lim = min(FCHUNK, NN - base);
    float a0 = 0.f, a1 = 0.f, a2 = 0.f, a3 = 0.f;
    int i = 0;
    for (; i + 4 <= lim; i += 4) {
        float w0 = g_bv[base + i] * inv,     w1 = g_bv[base + i + 1] * inv;
        float w2 = g_bv[base + i + 2] * inv, w3 = g_bv[base + i + 3] * inv;
        float h0 = ns[(size_t)(base + i) * HH + tid];
        float h1 = ns[(size_t)(base + i + 1) * HH + tid];
        float h2 = ns[(size_t)(base + i + 2) * HH + tid];
        float h3 = ns[(size_t)(base + i + 3) * HH + tid];
        a0 = fmaf(w0, h0, a0); a1 = fmaf(w1, h1, a1);
        a2 = fmaf(w2, h2, a2); a3 = fmaf(w3, h3, a3);
    }
    for (; i < lim; i++)
        a0 = fmaf(g_bv[base + i] * inv, ns[(size_t)(base + i) * HH + tid], a0);
    atomicAdd(&out[tid], (a0 + a1) + (a2 + a3));
}

// ---------------- launcher ----------------
extern "C" void kernel_launch(void* const* d_in, const int* in_sizes, int n_in,
                              void* d_out, int out_size) {
    const int*   node_ids = (const int*)d_in[0];
    const int*   edge_index = (const int*)d_in[1];
    const float* emb    = (const float*)d_in[2];
    const float* proj_w = (const float*)d_in[3];
    const float* edge_w = (const float*)d_in[4];
    const float* ln_g   = (const float*)d_in[5];
    const float* ln_b   = (const float*)d_in[6];
    const float* pool_w = (const float*)d_in[7];
    const float* pool_b = (const float*)d_in[8];
    const float* score_w = (const float*)d_in[9];
    float* out = (float*)d_out;
    const int* src = edge_index;
    const int* dst = edge_index + EE;

    float *p_ns, *p_ns2, *p_h;
    cudaGetSymbolAddress((void**)&p_ns, g_ns);
    cudaGetSymbolAddress((void**)&p_ns2, g_ns2);
    cudaGetSymbolAddress((void**)&p_h, g_h);

    dim3 gemm_grid((NN + 127) / 128, 2);
    int wpn_grid = (NN + 7) / 8;   // warp-per-node kernels

    // order chosen so sgemm_mma is the 4th launch (ncu -s 5 -c 1 slot)
    embed_kernel<<<NN, HH>>>(node_ids, emb);                         // 1
    init_kernel<<<(NN + 255) / 256, 256>>>(out);                     // 2
    deg_kernel<<<(EE + 255) / 256, 256>>>(dst);                      // 3
    sgemm_mma<<<gemm_grid, 256>>>(p_ns, proj_w, p_h, NN);            // 4 (profiled)
    scan_kernel<<<1, 1024>>>();                                      // 5
    scatter_kernel<<<(EE + 255) / 256, 256>>>(src, dst);             // 6
    ab_kernel<<<(NN * 32 + 255) / 256, 256>>>(p_h, edge_w);          // 7
    agg_kernel<<<wpn_grid, 256>>>(p_h, p_ns, p_ns2, ln_g, ln_b);     // 8

    // layer 1
    sgemm_mma<<<gemm_grid, 256>>>(p_ns2, proj_w + HH * HH, p_h, NN);
    ab_kernel<<<(NN * 32 + 255) / 256, 256>>>(p_h, edge_w + 2 * HH);
    agg_kernel<<<wpn_grid, 256>>>(p_h, p_ns2, p_ns, ln_g + HH, ln_b + HH);

    // pooling
    sgemm_mma<<<gemm_grid, 256>>>(p_ns, pool_w, p_h, NN);
    pool_s_kernel<<<wpn_grid, 256>>>(p_h, pool_b, score_w, node_ids);
    pool_exp_kernel<<<(NN + 255) / 256, 256>>>(node_ids);
    final_kernel<<<(NN + FCHUNK - 1) / FCHUNK, HH>>>(p_ns, out);
}

// round 8
// speedup vs baseline: 2.1934x; 1.0507x over previous
#include <cuda_runtime.h>
#include <cuda_bf16.h>
#include <math.h>
#include <stdint.h>

#define NN 20000
#define HH 256
#define EE 320000

// ---------------- scratch (device globals; no allocation allowed) ----------------
__device__ float g_ns[(size_t)NN * HH];
__device__ float g_ns2[(size_t)NN * HH];
__device__ float g_h[(size_t)NN * HH];
__device__ float g_av[NN];
__device__ float g_bv[NN];
__device__ int   g_deg[NN];
__device__ int   g_rowptr[NN + 1];
__device__ int   g_cursor[NN];
__device__ int   g_src_s[EE];
__device__ unsigned g_maxenc[4];
__device__ float g_pool_sum;

// order-preserving float<->uint map for atomicMax on floats
__device__ __forceinline__ unsigned enc_f(float x) {
    unsigned u = __float_as_uint(x);
    return (u & 0x80000000u) ? ~u : (u | 0x80000000u);
}
__device__ __forceinline__ float dec_f(unsigned u) {
    return (u & 0x80000000u) ? __uint_as_float(u & 0x7fffffffu)
                             : __uint_as_float(~u);
}

__device__ __forceinline__ float blk_sum(float v) {
    __shared__ float sh[32];
    int lane = threadIdx.x & 31, w = threadIdx.x >> 5;
#pragma unroll
    for (int o = 16; o; o >>= 1) v += __shfl_down_sync(0xffffffffu, v, o);
    if (!lane) sh[w] = v;
    __syncthreads();
    int nw = blockDim.x >> 5;
    float r = (threadIdx.x < nw) ? sh[threadIdx.x] : 0.f;
    if (w == 0) {
#pragma unroll
        for (int o = 16; o; o >>= 1) r += __shfl_down_sync(0xffffffffu, r, o);
        if (!lane) sh[0] = r;
    }
    __syncthreads();
    r = sh[0];
    __syncthreads();
    return r;
}

__device__ __forceinline__ float warp_sum(float v) {
#pragma unroll
    for (int o = 16; o; o >>= 1) v += __shfl_xor_sync(0xffffffffu, v, o);
    return v;
}

// ---------------- setup kernels ----------------
__global__ void init_kernel(float* out) {
    int i = blockIdx.x * blockDim.x + threadIdx.x;
    if (i < NN) g_deg[i] = 0;
    if (blockIdx.x == 0) {
        if (threadIdx.x < 4) g_maxenc[threadIdx.x] = 0x007FFFFFu; // enc(-inf)
        if (threadIdx.x == 4) g_pool_sum = 0.f;
        if (threadIdx.x < HH) out[threadIdx.x] = 0.f;
    }
}

__global__ void deg_kernel(const int* __restrict__ dst) {
    int e = blockIdx.x * blockDim.x + threadIdx.x;
    if (e < EE) atomicAdd(&g_deg[dst[e]], 1);
}

__global__ void scan_kernel() {
    __shared__ int ssum[1024];
    const int CH = (NN + 1023) / 1024; // 20
    int tid = threadIdx.x;
    int start = tid * CH;
    int local[32];
    int s = 0;
#pragma unroll
    for (int i = 0; i < CH; i++) {
        int idx = start + i;
        int d = (idx < NN) ? g_deg[idx] : 0;
        local[i] = s;
        s += d;
    }
    ssum[tid] = s;
    __syncthreads();
    for (int off = 1; off < 1024; off <<= 1) {
        int v = 0;
        if (tid >= off) v = ssum[tid - off];
        __syncthreads();
        if (tid >= off) ssum[tid] += v;
        __syncthreads();
    }
    int prefix = ssum[tid] - s;
#pragma unroll
    for (int i = 0; i < CH; i++) {
        int idx = start + i;
        if (idx < NN) {
            int p = prefix + local[i];
            g_rowptr[idx] = p;
            g_cursor[idx] = p;
        }
    }
    if (tid == 1023) g_rowptr[NN] = ssum[1023];
}

__global__ void scatter_kernel(const int* __restrict__ src, const int* __restrict__ dst) {
    int e = blockIdx.x * blockDim.x + threadIdx.x;
    if (e < EE) {
        int d = dst[e];
        int pos = atomicAdd(&g_cursor[d], 1);
        g_src_s[pos] = src[e];
    }
}

__global__ void embed_kernel(const int* __restrict__ node_ids, const float* __restrict__ emb) {
    int n = blockIdx.x;
    int t = threadIdx.x;
    g_ns[(size_t)n * HH + t] = emb[(size_t)node_ids[n] * HH + t];
}

// ---------------- TF32 mma.sync SGEMM (cp.async pipelined) ----------------
// C[M,256] = A[M,256] * B[256,256]^T. CTA 128x128, BK=16, 8 warps (2x4),
// warp tile 64x32 of m16n8k8. Raw f32 fed to tf32 mma (HW truncation).
#define SPAD 20  // smem row stride in floats -> conflict-free fragment loads

__device__ __forceinline__ void mma_tf32(float* c, const uint32_t* a, const uint32_t* b) {
    asm volatile(
        "mma.sync.aligned.m16n8k8.row.col.f32.tf32.tf32.f32 "
        "{%0,%1,%2,%3}, {%4,%5,%6,%7}, {%8,%9}, {%0,%1,%2,%3};"
        : "+f"(c[0]), "+f"(c[1]), "+f"(c[2]), "+f"(c[3])
        : "r"(a[0]), "r"(a[1]), "r"(a[2]), "r"(a[3]), "r"(b[0]), "r"(b[1]));
}

__device__ __forceinline__ void cp16(float* smem_dst, const float* gsrc, bool valid) {
    uint32_t s = (uint32_t)__cvta_generic_to_shared(smem_dst);
    int sz = valid ? 16 : 0;
    asm volatile("cp.async.cg.shared.global [%0], [%1], 16, %2;"
                 :: "r"(s), "l"(gsrc), "r"(sz));
}

__global__ __launch_bounds__(256) void sgemm_mma(const float* __restrict__ A,
                                                 const float* __restrict__ B,
                                                 float* __restrict__ C, int M) {
    __shared__ float As[2][128 * SPAD];
    __shared__ float Bs[2][128 * SPAD];
    int tid = threadIdx.x;
    int lane = tid & 31, w = tid >> 5;
    int wm = w & 1, wn = w >> 1;           // warp grid 2 (m) x 4 (n)
    int g = lane >> 2, t4 = lane & 3;      // group-id, thread-in-group
    int bm = blockIdx.x * 128, bn = blockIdx.y * 128;

    float c[4][4][4];
#pragma unroll
    for (int mi = 0; mi < 4; mi++)
#pragma unroll
        for (int ni = 0; ni < 4; ni++)
#pragma unroll
            for (int j = 0; j < 4; j++) c[mi][ni][j] = 0.f;

    int r0 = tid >> 2, q0 = tid & 3;       // 64 rows x 4 quads per 256 threads
    int ga0 = bm + r0, ga1 = bm + r0 + 64;
    bool v0 = ga0 < M, v1 = ga1 < M;
    const float* pA0 = &A[(size_t)(v0 ? ga0 : 0) * HH + q0 * 4];
    const float* pA1 = &A[(size_t)(v1 ? ga1 : 0) * HH + q0 * 4];
    const float* pB0 = &B[(size_t)(bn + r0) * HH + q0 * 4];
    const float* pB1 = &B[(size_t)(bn + r0 + 64) * HH + q0 * 4];
    float* sA0 = &As[0][r0 * SPAD + q0 * 4];
    float* sA1 = &As[0][(r0 + 64) * SPAD + q0 * 4];
    float* sB0 = &Bs[0][r0 * SPAD + q0 * 4];
    float* sB1 = &Bs[0][(r0 + 64) * SPAD + q0 * 4];
    const int SB = 128 * SPAD;

    // prologue: issue k-tile 0 into buffer 0
    cp16(sA0, pA0, v0);
    cp16(sA1, pA1, v1);
    cp16(sB0, pB0, true);
    cp16(sB1, pB1, true);
    asm volatile("cp.async.commit_group;" ::: "memory");

#pragma unroll 1
    for (int it = 0; it < 16; it++) {
        asm volatile("cp.async.wait_group 0;" ::: "memory");
        __syncthreads();
        int st = it & 1;
        // issue next k-tile into the other buffer (overlaps compute)
        if (it < 15) {
            int nst = (it + 1) & 1;
            int k0 = (it + 1) * 16;
            cp16(sA0 + nst * SB, pA0 + k0, v0);
            cp16(sA1 + nst * SB, pA1 + k0, v1);
            cp16(sB0 + nst * SB, pB0 + k0, true);
            cp16(sB1 + nst * SB, pB1 + k0, true);
            asm volatile("cp.async.commit_group;" ::: "memory");
        }
        const uint32_t* Asb = (const uint32_t*)&As[st][0];
        const uint32_t* Bsb = (const uint32_t*)&Bs[st][0];
#pragma unroll
        for (int ks = 0; ks < 2; ks++) {
            int kb = ks * 8 + t4;
            uint32_t af[4][4];
#pragma unroll
            for (int mi = 0; mi < 4; mi++) {
                int rr = wm * 64 + mi * 16 + g;
                af[mi][0] = Asb[rr * SPAD + kb];
                af[mi][1] = Asb[(rr + 8) * SPAD + kb];
                af[mi][2] = Asb[rr * SPAD + kb + 4];
                af[mi][3] = Asb[(rr + 8) * SPAD + kb + 4];
            }
            uint32_t bf[4][2];
#pragma unroll
            for (int ni = 0; ni < 4; ni++) {
                int cc = wn * 32 + ni * 8 + g;
                bf[ni][0] = Bsb[cc * SPAD + kb];
                bf[ni][1] = Bsb[cc * SPAD + kb + 4];
            }
#pragma unroll
            for (int mi = 0; mi < 4; mi++)
#pragma unroll
                for (int ni = 0; ni < 4; ni++)
                    mma_tf32(c[mi][ni], af[mi], bf[ni]);
        }
        __syncthreads();
    }

#pragma unroll
    for (int mi = 0; mi < 4; mi++) {
#pragma unroll
        for (int ni = 0; ni < 4; ni++) {
            int row = bm + wm * 64 + mi * 16 + g;
            int col = bn + wn * 32 + ni * 8 + 2 * t4;
            if (row < M)
                *(float2*)&C[(size_t)row * HH + col] = make_float2(c[mi][ni][0], c[mi][ni][1]);
            if (row + 8 < M)
                *(float2*)&C[(size_t)(row + 8) * HH + col] = make_float2(c[mi][ni][2], c[mi][ni][3]);
        }
    }
}

// ---------------- per-layer kernels ----------------
__global__ void ab_kernel(const float* __restrict__ hbuf, const float* __restrict__ ew) {
    int wg = (blockIdx.x * blockDim.x + threadIdx.x) >> 5;
    int lane = threadIdx.x & 31;
    if (wg >= NN) return;
    const float* row = hbuf + (size_t)wg * HH;
    float a = 0.f, b = 0.f;
#pragma unroll
    for (int k = lane; k < HH; k += 32) {
        float hv = row[k];
        a = fmaf(hv, ew[k], a);
        b = fmaf(hv, ew[HH + k], b);
    }
#pragma unroll
    for (int o = 16; o; o >>= 1) {
        a += __shfl_down_sync(0xffffffffu, a, o);
        b += __shfl_down_sync(0xffffffffu, b, o);
    }
    if (!lane) { g_av[wg] = a; g_bv[wg] = b; }
}

// warp-per-node fused aggregation: inline softmax weights (global max cancels
// up to the +1e-6 term, ~1e-7 relative), weighted gather-sum, residual, LN, GELU.
__global__ __launch_bounds__(256) void agg_kernel(const float* __restrict__ hbuf,
                                                  const float* __restrict__ nsin,
                                                  float* __restrict__ nsout,
                                                  const float* __restrict__ gamma,
                                                  const float* __restrict__ beta) {
    int wid = threadIdx.x >> 5, lane = threadIdx.x & 31;
    int n = blockIdx.x * 8 + wid;
    if (n >= NN) return;
    int beg = g_rowptr[n], end = g_rowptr[n + 1];
    float bvn = g_bv[n];

    float4 acc0 = make_float4(0.f, 0.f, 0.f, 0.f);
    float4 acc1 = make_float4(0.f, 0.f, 0.f, 0.f);
    float wlocal = 0.f;

    for (int base = beg; base < end; base += 32) {
        int cnt = min(32, end - base);
        int sv = 0;
        float wv = 0.f;
        if (lane < cnt) {
            sv = g_src_s[base + lane];
            float sc = g_av[sv] + bvn;
            sc = (sc >= 0.f) ? sc : 0.2f * sc;
            wv = expf(sc);
        }
        wlocal += wv;
        int j = 0;
        for (; j + 2 <= cnt; j += 2) {
            int   sj0 = __shfl_sync(0xffffffffu, sv, j);
            int   sj1 = __shfl_sync(0xffffffffu, sv, j + 1);
            float wj0 = __shfl_sync(0xffffffffu, wv, j);
            float wj1 = __shfl_sync(0xffffffffu, wv, j + 1);
            const float4* ra = (const float4*)&hbuf[(size_t)sj0 * HH];
            const float4* rb = (const float4*)&hbuf[(size_t)sj1 * HH];
            float4 a0 = ra[lane], a1 = ra[32 + lane];
            float4 b0 = rb[lane], b1 = rb[32 + lane];
            acc0.x = fmaf(a0.x, wj0, acc0.x); acc0.y = fmaf(a0.y, wj0, acc0.y);
            acc0.z = fmaf(a0.z, wj0, acc0.z); acc0.w = fmaf(a0.w, wj0, acc0.w);
            acc1.x = fmaf(a1.x, wj0, acc1.x); acc1.y = fmaf(a1.y, wj0, acc1.y);
            acc1.z = fmaf(a1.z, wj0, acc1.z); acc1.w = fmaf(a1.w, wj0, acc1.w);
            acc0.x = fmaf(b0.x, wj1, acc0.x); acc0.y = fmaf(b0.y, wj1, acc0.y);
            acc0.z = fmaf(b0.z, wj1, acc0.z); acc0.w = fmaf(b0.w, wj1, acc0.w);
            acc1.x = fmaf(b1.x, wj1, acc1.x); acc1.y = fmaf(b1.y, wj1, acc1.y);
            acc1.z = fmaf(b1.z, wj1, acc1.z); acc1.w = fmaf(b1.w, wj1, acc1.w);
        }
        if (j < cnt) {
            int   sj = __shfl_sync(0xffffffffu, sv, j);
            float wj = __shfl_sync(0xffffffffu, wv, j);
            const float4* ra = (const float4*)&hbuf[(size_t)sj * HH];
            float4 a0 = ra[lane], a1 = ra[32 + lane];
            acc0.x = fmaf(a0.x, wj, acc0.x); acc0.y = fmaf(a0.y, wj, acc0.y);
            acc0.z = fmaf(a0.z, wj, acc0.z); acc0.w = fmaf(a0.w, wj, acc0.w);
            acc1.x = fmaf(a1.x, wj, acc1.x); acc1.y = fmaf(a1.y, wj, acc1.y);
            acc1.z = fmaf(a1.z, wj, acc1.z); acc1.w = fmaf(a1.w, wj, acc1.w);
        }
    }
    float denom = warp_sum(wlocal) + 1e-6f;
    float inv = 1.f / denom;

    const float4* ns4 = (const float4*)&nsin[(size_t)n * HH];
    float4 r0 = ns4[lane], r1 = ns4[32 + lane];
    float x[8];
    x[0] = fmaf(acc0.x, inv, r0.x); x[1] = fmaf(acc0.y, inv, r0.y);
    x[2] = fmaf(acc0.z, inv, r0.z); x[3] = fmaf(acc0.w, inv, r0.w);
    x[4] = fmaf(acc1.x, inv, r1.x); x[5] = fmaf(acc1.y, inv, r1.y);
    x[6] = fmaf(acc1.z, inv, r1.z); x[7] = fmaf(acc1.w, inv, r1.w);

    float lsum = ((x[0] + x[1]) + (x[2] + x[3])) + ((x[4] + x[5]) + (x[6] + x[7]));
    float m = warp_sum(lsum) * (1.f / HH);
    float vsum = 0.f;
#pragma unroll
    for (int i = 0; i < 8; i++) {
        float d = x[i] - m;
        vsum = fmaf(d, d, vsum);
    }
    float var = warp_sum(vsum) * (1.f / HH);
    float rs = rsqrtf(var + 1e-5f);

    const float4* gg = (const float4*)&gamma[0];
    const float4* bb = (const float4*)&beta[0];
    float4 g0 = gg[lane], g1 = gg[32 + lane];
    float4 b0 = bb[lane], b1 = bb[32 + lane];
    float gam[8] = {g0.x, g0.y, g0.z, g0.w, g1.x, g1.y, g1.z, g1.w};
    float bet[8] = {b0.x, b0.y, b0.z, b0.w, b1.x, b1.y, b1.z, b1.w};
    float o[8];
#pragma unroll
    for (int i = 0; i < 8; i++) {
        float y = fmaf((x[i] - m) * rs, gam[i], bet[i]);
        o[i] = 0.5f * y * (1.f + erff(y * 0.70710678118654752440f));
    }
    float4* out4 = (float4*)&nsout[(size_t)n * HH];
    out4[lane] = make_float4(o[0], o[1], o[2], o[3]);
    out4[32 + lane] = make_float4(o[4], o[5], o[6], o[7]);
}

// ---------------- pooling ----------------
__global__ __launch_bounds__(256) void pool_s_kernel(const float* __restrict__ P,
                                                     const float* __restrict__ pb,
                                                     const float* __restrict__ sw,
                                                     const int* __restrict__ node_ids) {
    int wid = threadIdx.x >> 5, lane = threadIdx.x & 31;
    int n = blockIdx.x * 8 + wid;
    if (n >= NN) return;
    const float4* P4 = (const float4*)&P[(size_t)n * HH];
    const float4* pb4 = (const float4*)&pb[0];
    const float4* sw4 = (const float4*)&sw[0];
    float4 p0 = P4[lane], p1 = P4[32 + lane];
    float4 c0 = pb4[lane], c1 = pb4[32 + lane];
    float4 w0 = sw4[lane], w1 = sw4[32 + lane];
    float v = tanhf(p0.x + c0.x) * w0.x + tanhf(p0.y + c0.y) * w0.y +
              tanhf(p0.z + c0.z) * w0.z + tanhf(p0.w + c0.w) * w0.w +
              tanhf(p1.x + c1.x) * w1.x + tanhf(p1.y + c1.y) * w1.y +
              tanhf(p1.z + c1.z) * w1.z + tanhf(p1.w + c1.w) * w1.w;
    float s = warp_sum(v);
    if (!lane) {
        if (node_ids[n] != 0) {
            g_av[n] = s;
            atomicMax(&g_maxenc[0], enc_f(s));
        } else {
            g_av[n] = 0.f;
        }
    }
}

__global__ void pool_exp_kernel(const int* __restrict__ node_ids) {
    int i = blockIdx.x * blockDim.x + threadIdx.x;
    float e = 0.f;
    if (i < NN) {
        float smax = dec_f(g_maxenc[0]);
        if (node_ids[i] != 0) e = expf(g_av[i] - smax);
        g_bv[i] = e;
    }
    float r = blk_sum(e);
    if (threadIdx.x == 0) atomicAdd(&g_pool_sum, r);
}

#define FCHUNK 64
__global__ __launch_bounds__(HH) void final_kernel(const float* __restrict__ ns, float* __restrict__ out) {
    int base = blockIdx.x * FCHUNK;
    int tid = threadIdx.x;
    float sum = g_pool_sum;
    float inv = (sum > 0.f) ? 1.f / sum : 0.f;
    if (tid < FCHUNK) {
        int n = base + tid;
        if (n < NN) out[HH + n] = g_bv[n] * inv;
    }
    int lim = min(FCHUNK, NN - base);
    float a0 = 0.f, a1 = 0.f, a2 = 0.f, a3 = 0.f;
    int i = 0;
    for (; i + 4 <= lim; i += 4) {
        float w0 = g_bv[base + i] * inv,     w1 = g_bv[base + i + 1] * inv;
        float w2 = g_bv[base + i + 2] * inv, w3 = g_bv[base + i + 3] * inv;
        float h0 = ns[(size_t)(base + i) * HH + tid];
        float h1 = ns[(size_t)(base + i + 1) * HH + tid];
        float h2 = ns[(size_t)(base + i + 2) * HH + tid];
        float h3 = ns[(size_t)(base + i + 3) * HH + tid];
        a0 = fmaf(w0, h0, a0); a1 = fmaf(w1, h1, a1);
        a2 = fmaf(w2, h2, a2); a3 = fmaf(w3, h3, a3);
    }
    for (; i < lim; i++)
        a0 = fmaf(g_bv[base + i] * inv, ns[(size_t)(base + i) * HH + tid], a0);
    atomicAdd(&out[tid], (a0 + a1) + (a2 + a3));
}

// ---------------- launcher ----------------
extern "C" void kernel_launch(void* const* d_in, const int* in_sizes, int n_in,
                              void* d_out, int out_size) {
    const int*   node_ids = (const int*)d_in[0];
    const int*   edge_index = (const int*)d_in[1];
    const float* emb    = (const float*)d_in[2];
    const float* proj_w = (const float*)d_in[3];
    const float* edge_w = (const float*)d_in[4];
    const float* ln_g   = (const float*)d_in[5];
    const float* ln_b   = (const float*)d_in[6];
    const float* pool_w = (const float*)d_in[7];
    const float* pool_b = (const float*)d_in[8];
    const float* score_w = (const float*)d_in[9];
    float* out = (float*)d_out;
    const int* src = edge_index;
    const int* dst = edge_index + EE;

    float *p_ns, *p_ns2, *p_h;
    cudaGetSymbolAddress((void**)&p_ns, g_ns);
    cudaGetSymbolAddress((void**)&p_ns2, g_ns2);
    cudaGetSymbolAddress((void**)&p_h, g_h);

    dim3 gemm_grid((NN + 127) / 128, 2);
    int wpn_grid = (NN + 7) / 8;   // warp-per-node kernels

    // order chosen so sgemm_mma is the 4th launch (ncu -s 5 -c 1 slot)
    embed_kernel<<<NN, HH>>>(node_ids, emb);                         // 1
    init_kernel<<<(NN + 255) / 256, 256>>>(out);                     // 2
    deg_kernel<<<(EE + 255) / 256, 256>>>(dst);                      // 3
    sgemm_mma<<<gemm_grid, 256>>>(p_ns, proj_w, p_h, NN);            // 4 (profiled)
    scan_kernel<<<1, 1024>>>();                                      // 5
    scatter_kernel<<<(EE + 255) / 256, 256>>>(src, dst);             // 6
    ab_kernel<<<(NN * 32 + 255) / 256, 256>>>(p_h, edge_w);          // 7
    agg_kernel<<<wpn_grid, 256>>>(p_h, p_ns, p_ns2, ln_g, ln_b);     // 8

    // layer 1
    sgemm_mma<<<gemm_grid, 256>>>(p_ns2, proj_w + HH * HH, p_h, NN);
    ab_kernel<<<(NN * 32 + 255) / 256, 256>>>(p_h, edge_w + 2 * HH);
    agg_kernel<<<wpn_grid, 256>>>(p_h, p_ns2, p_ns, ln_g + HH, ln_b + HH);

    // pooling
    sgemm_mma<<<gemm_grid, 256>>>(p_ns, pool_w, p_h, NN);
    pool_s_kernel<<<wpn_grid, 256>>>(p_h, pool_b, score_w, node_ids);
    pool_exp_kernel<<<(NN + 255) / 256, 256>>>(node_ids);
    final_kernel<<<(NN + FCHUNK - 1) / FCHUNK, HH>>>(p_ns, out);
}

// round 12
// speedup vs baseline: 2.3858x; 1.0877x over previous
#include <cuda_runtime.h>
#include <cuda_bf16.h>
#include <math.h>
#include <stdint.h>

#define NN 20000
#define HH 256
#define EE 320000

// ---------------- scratch (device globals; no allocation allowed) ----------------
__device__ float g_ns[(size_t)NN * HH];
__device__ float g_ns2[(size_t)NN * HH];
__device__ float g_h[(size_t)NN * HH];
__device__ float g_a0[NN], g_b0[NN];   // layer0 edge-score halves
__device__ float g_a1[NN], g_b1[NN];   // layer1 edge-score halves
__device__ float g_sp[NN];             // pooling scores
__device__ float g_bv[NN];             // pooling exp weights
__device__ int   g_deg[NN];
__device__ int   g_rowptr[NN + 1];
__device__ int   g_cursor[NN];
__device__ int   g_src_s[EE];
__device__ float g_pool_sum;

__device__ __forceinline__ float blk_sum(float v) {
    __shared__ float sh[32];
    int lane = threadIdx.x & 31, w = threadIdx.x >> 5;
#pragma unroll
    for (int o = 16; o; o >>= 1) v += __shfl_down_sync(0xffffffffu, v, o);
    if (!lane) sh[w] = v;
    __syncthreads();
    int nw = blockDim.x >> 5;
    float r = (threadIdx.x < nw) ? sh[threadIdx.x] : 0.f;
    if (w == 0) {
#pragma unroll
        for (int o = 16; o; o >>= 1) r += __shfl_down_sync(0xffffffffu, r, o);
        if (!lane) sh[0] = r;
    }
    __syncthreads();
    r = sh[0];
    __syncthreads();
    return r;
}

__device__ __forceinline__ float warp_sum(float v) {
#pragma unroll
    for (int o = 16; o; o >>= 1) v += __shfl_xor_sync(0xffffffffu, v, o);
    return v;
}

// ---------------- setup kernels ----------------
__global__ void init_kernel(float* out) {
    int i = blockIdx.x * blockDim.x + threadIdx.x;
    if (i < NN) {
        g_deg[i] = 0;
        g_a0[i] = 0.f; g_b0[i] = 0.f;
        g_a1[i] = 0.f; g_b1[i] = 0.f;
        g_sp[i] = 0.f;
    }
    if (i < HH) out[i] = 0.f;
    if (i == 0) g_pool_sum = 0.f;
}

__global__ void deg_kernel(const int* __restrict__ dst) {
    int e = blockIdx.x * blockDim.x + threadIdx.x;
    if (e < EE) atomicAdd(&g_deg[dst[e]], 1);
}

__global__ void scan_kernel() {
    __shared__ int ssum[1024];
    const int CH = (NN + 1023) / 1024; // 20
    int tid = threadIdx.x;
    int start = tid * CH;
    int local[32];
    int s = 0;
#pragma unroll
    for (int i = 0; i < CH; i++) {
        int idx = start + i;
        int d = (idx < NN) ? g_deg[idx] : 0;
        local[i] = s;
        s += d;
    }
    ssum[tid] = s;
    __syncthreads();
    for (int off = 1; off < 1024; off <<= 1) {
        int v = 0;
        if (tid >= off) v = ssum[tid - off];
        __syncthreads();
        if (tid >= off) ssum[tid] += v;
        __syncthreads();
    }
    int prefix = ssum[tid] - s;
#pragma unroll
    for (int i = 0; i < CH; i++) {
        int idx = start + i;
        if (idx < NN) {
            int p = prefix + local[i];
            g_rowptr[idx] = p;
            g_cursor[idx] = p;
        }
    }
    if (tid == 1023) g_rowptr[NN] = ssum[1023];
}

__global__ void scatter_kernel(const int* __restrict__ src, const int* __restrict__ dst) {
    int e = blockIdx.x * blockDim.x + threadIdx.x;
    if (e < EE) {
        int d = dst[e];
        int pos = atomicAdd(&g_cursor[d], 1);
        g_src_s[pos] = src[e];
    }
}

__global__ void embed_kernel(const int* __restrict__ node_ids, const float* __restrict__ emb) {
    int n = blockIdx.x;
    int t = threadIdx.x;
    g_ns[(size_t)n * HH + t] = emb[(size_t)node_ids[n] * HH + t];
}

// ---------------- TF32 mma.sync SGEMM, 2-stage cp.async (static smem), fused epilogues ----
// C[M,256] = A[M,256] * B[256,256]^T. CTA 128x128, BK=16, 8 warps (2x4),
// warp tile 64x32 of m16n8k8. Raw f32 fed to tf32 mma (HW truncation).
// MODE 0: write C and accumulate a[row]=C[row]·w1, b[row]=C[row]·w2 (edge MLP halves).
// MODE 1: no C write; accumulate s[row]=sum(tanh(C[row]+w1)*w2) (attention pooling).
#define SPAD 20

__device__ __forceinline__ void mma_tf32(float* c, const uint32_t* a, const uint32_t* b) {
    asm volatile(
        "mma.sync.aligned.m16n8k8.row.col.f32.tf32.tf32.f32 "
        "{%0,%1,%2,%3}, {%4,%5,%6,%7}, {%8,%9}, {%0,%1,%2,%3};"
        : "+f"(c[0]), "+f"(c[1]), "+f"(c[2]), "+f"(c[3])
        : "r"(a[0]), "r"(a[1]), "r"(a[2]), "r"(a[3]), "r"(b[0]), "r"(b[1]));
}

__device__ __forceinline__ void cp16(float* smem_dst, const float* gsrc, bool valid) {
    uint32_t s = (uint32_t)__cvta_generic_to_shared(smem_dst);
    int sz = valid ? 16 : 0;  // sz=0 -> 16B zero-fill
    asm volatile("cp.async.cg.shared.global [%0], [%1], 16, %2;"
                 :: "r"(s), "l"(gsrc), "r"(sz));
}

template <int MODE>
__global__ __launch_bounds__(256) void sgemm_mma(const float* __restrict__ A,
                                                 const float* __restrict__ B,
                                                 float* __restrict__ C, int M,
                                                 const float* __restrict__ w1,
                                                 const float* __restrict__ w2,
                                                 float* __restrict__ accA,
                                                 float* __restrict__ accB) {
    __shared__ float As[2][128 * SPAD];
    __shared__ float Bs[2][128 * SPAD];
    int tid = threadIdx.x;
    int lane = tid & 31, w = tid >> 5;
    int wm = w & 1, wn = w >> 1;           // warp grid 2 (m) x 4 (n)
    int g = lane >> 2, t4 = lane & 3;      // group-id, thread-in-group
    int bm = blockIdx.x * 128, bn = blockIdx.y * 128;

    float c[4][4][4];
#pragma unroll
    for (int mi = 0; mi < 4; mi++)
#pragma unroll
        for (int ni = 0; ni < 4; ni++)
#pragma unroll
            for (int j = 0; j < 4; j++) c[mi][ni][j] = 0.f;

    int r0 = tid >> 2, q0 = tid & 3;
    int ga0 = bm + r0, ga1 = bm + r0 + 64;
    bool v0 = ga0 < M, v1 = ga1 < M;
    const float* pA0 = &A[(size_t)(v0 ? ga0 : 0) * HH + q0 * 4];
    const float* pA1 = &A[(size_t)(v1 ? ga1 : 0) * HH + q0 * 4];
    const float* pB0 = &B[(size_t)(bn + r0) * HH + q0 * 4];
    const float* pB1 = &B[(size_t)(bn + r0 + 64) * HH + q0 * 4];
    float* sA0 = &As[0][r0 * SPAD + q0 * 4];
    float* sA1 = &As[0][(r0 + 64) * SPAD + q0 * 4];
    float* sB0 = &Bs[0][r0 * SPAD + q0 * 4];
    float* sB1 = &Bs[0][(r0 + 64) * SPAD + q0 * 4];
    const int SB = 128 * SPAD;

    // prologue: issue k-tile 0 into buffer 0
    cp16(sA0, pA0, v0);
    cp16(sA1, pA1, v1);
    cp16(sB0, pB0, true);
    cp16(sB1, pB1, true);
    asm volatile("cp.async.commit_group;" ::: "memory");

#pragma unroll 1
    for (int it = 0; it < 16; it++) {
        asm volatile("cp.async.wait_group 0;" ::: "memory");
        __syncthreads();
        int st = it & 1;
        if (it < 15) {
            int nst = (it + 1) & 1;
            int k0 = (it + 1) * 16;
            cp16(sA0 + nst * SB, pA0 + k0, v0);
            cp16(sA1 + nst * SB, pA1 + k0, v1);
            cp16(sB0 + nst * SB, pB0 + k0, true);
            cp16(sB1 + nst * SB, pB1 + k0, true);
            asm volatile("cp.async.commit_group;" ::: "memory");
        }
        const uint32_t* Asb = (const uint32_t*)&As[st][0];
        const uint32_t* Bsb = (const uint32_t*)&Bs[st][0];
#pragma unroll
        for (int ks = 0; ks < 2; ks++) {
            int kb = ks * 8 + t4;
            uint32_t af[4][4];
#pragma unroll
            for (int mi = 0; mi < 4; mi++) {
                int rr = wm * 64 + mi * 16 + g;
                af[mi][0] = Asb[rr * SPAD + kb];
                af[mi][1] = Asb[(rr + 8) * SPAD + kb];
                af[mi][2] = Asb[rr * SPAD + kb + 4];
                af[mi][3] = Asb[(rr + 8) * SPAD + kb + 4];
            }
            uint32_t bf[4][2];
#pragma unroll
            for (int ni = 0; ni < 4; ni++) {
                int cc = wn * 32 + ni * 8 + g;
                bf[ni][0] = Bsb[cc * SPAD + kb];
                bf[ni][1] = Bsb[cc * SPAD + kb + 4];
            }
#pragma unroll
            for (int mi = 0; mi < 4; mi++)
#pragma unroll
                for (int ni = 0; ni < 4; ni++)
                    mma_tf32(c[mi][ni], af[mi], bf[ni]);
        }
        __syncthreads();
    }

    // epilogue: C write (MODE 0) + fused row reductions
#pragma unroll
    for (int mi = 0; mi < 4; mi++) {
        int row = bm + wm * 64 + mi * 16 + g;
        float palo = 0.f, pahi = 0.f, pblo = 0.f, pbhi = 0.f;
#pragma unroll
        for (int ni = 0; ni < 4; ni++) {
            int col = bn + wn * 32 + ni * 8 + 2 * t4;
            if (MODE == 0) {
                float e0 = __ldg(&w1[col]), e1 = __ldg(&w1[col + 1]);
                float f0 = __ldg(&w2[col]), f1 = __ldg(&w2[col + 1]);
                palo += c[mi][ni][0] * e0 + c[mi][ni][1] * e1;
                pahi += c[mi][ni][2] * e0 + c[mi][ni][3] * e1;
                pblo += c[mi][ni][0] * f0 + c[mi][ni][1] * f1;
                pbhi += c[mi][ni][2] * f0 + c[mi][ni][3] * f1;
                if (row < M)
                    *(float2*)&C[(size_t)row * HH + col] = make_float2(c[mi][ni][0], c[mi][ni][1]);
                if (row + 8 < M)
                    *(float2*)&C[(size_t)(row + 8) * HH + col] = make_float2(c[mi][ni][2], c[mi][ni][3]);
            } else {
                float p0 = __ldg(&w1[col]), p1 = __ldg(&w1[col + 1]);
                float s0 = __ldg(&w2[col]), s1 = __ldg(&w2[col + 1]);
                palo += tanhf(c[mi][ni][0] + p0) * s0 + tanhf(c[mi][ni][1] + p1) * s1;
                pahi += tanhf(c[mi][ni][2] + p0) * s0 + tanhf(c[mi][ni][3] + p1) * s1;
            }
        }
        // reduce across t4 (lane bits 0-1)
        palo += __shfl_xor_sync(0xffffffffu, palo, 1);
        palo += __shfl_xor_sync(0xffffffffu, palo, 2);
        pahi += __shfl_xor_sync(0xffffffffu, pahi, 1);
        pahi += __shfl_xor_sync(0xffffffffu, pahi, 2);
        if (MODE == 0) {
            pblo += __shfl_xor_sync(0xffffffffu, pblo, 1);
            pblo += __shfl_xor_sync(0xffffffffu, pblo, 2);
            pbhi += __shfl_xor_sync(0xffffffffu, pbhi, 1);
            pbhi += __shfl_xor_sync(0xffffffffu, pbhi, 2);
        }
        if (t4 == 0) {
            if (row < M) {
                atomicAdd(&accA[row], palo);
                if (MODE == 0) atomicAdd(&accB[row], pblo);
            }
            if (row + 8 < M) {
                atomicAdd(&accA[row + 8], pahi);
                if (MODE == 0) atomicAdd(&accB[row + 8], pbhi);
            }
        }
    }
}

// ---------------- per-layer kernels ----------------
// warp-per-node fused aggregation: inline softmax weights (global max cancels
// up to the +1e-6 term, ~1e-7 relative), weighted gather-sum, residual, LN, GELU.
__global__ __launch_bounds__(256) void agg_kernel(const float* __restrict__ hbuf,
                                                  const float* __restrict__ nsin,
                                                  float* __restrict__ nsout,
                                                  const float* __restrict__ gamma,
                                                  const float* __restrict__ beta,
                                                  const float* __restrict__ av,
                                                  const float* __restrict__ bv) {
    int wid = threadIdx.x >> 5, lane = threadIdx.x & 31;
    int n = blockIdx.x * 8 + wid;
    if (n >= NN) return;
    int beg = g_rowptr[n], end = g_rowptr[n + 1];
    float bvn = bv[n];

    float4 acc0 = make_float4(0.f, 0.f, 0.f, 0.f);
    float4 acc1 = make_float4(0.f, 0.f, 0.f, 0.f);
    float wlocal = 0.f;

    for (int base = beg; base < end; base += 32) {
        int cnt = min(32, end - base);
        int sv = 0;
        float wv = 0.f;
        if (lane < cnt) {
            sv = g_src_s[base + lane];
            float sc = av[sv] + bvn;
            sc = (sc >= 0.f) ? sc : 0.2f * sc;
            wv = expf(sc);
        }
        wlocal += wv;
        int j = 0;
        for (; j + 2 <= cnt; j += 2) {
            int   sj0 = __shfl_sync(0xffffffffu, sv, j);
            int   sj1 = __shfl_sync(0xffffffffu, sv, j + 1);
            float wj0 = __shfl_sync(0xffffffffu, wv, j);
            float wj1 = __shfl_sync(0xffffffffu, wv, j + 1);
            const float4* ra = (const float4*)&hbuf[(size_t)sj0 * HH];
            const float4* rb = (const float4*)&hbuf[(size_t)sj1 * HH];
            float4 a0 = ra[lane], a1 = ra[32 + lane];
            float4 b0 = rb[lane], b1 = rb[32 + lane];
            acc0.x = fmaf(a0.x, wj0, acc0.x); acc0.y = fmaf(a0.y, wj0, acc0.y);
            acc0.z = fmaf(a0.z, wj0, acc0.z); acc0.w = fmaf(a0.w, wj0, acc0.w);
            acc1.x = fmaf(a1.x, wj0, acc1.x); acc1.y = fmaf(a1.y, wj0, acc1.y);
            acc1.z = fmaf(a1.z, wj0, acc1.z); acc1.w = fmaf(a1.w, wj0, acc1.w);
            acc0.x = fmaf(b0.x, wj1, acc0.x); acc0.y = fmaf(b0.y, wj1, acc0.y);
            acc0.z = fmaf(b0.z, wj1, acc0.z); acc0.w = fmaf(b0.w, wj1, acc0.w);
            acc1.x = fmaf(b1.x, wj1, acc1.x); acc1.y = fmaf(b1.y, wj1, acc1.y);
            acc1.z = fmaf(b1.z, wj1, acc1.z); acc1.w = fmaf(b1.w, wj1, acc1.w);
        }
        if (j < cnt) {
            int   sj = __shfl_sync(0xffffffffu, sv, j);
            float wj = __shfl_sync(0xffffffffu, wv, j);
            const float4* ra = (const float4*)&hbuf[(size_t)sj * HH];
            float4 a0 = ra[lane], a1 = ra[32 + lane];
            acc0.x = fmaf(a0.x, wj, acc0.x); acc0.y = fmaf(a0.y, wj, acc0.y);
            acc0.z = fmaf(a0.z, wj, acc0.z); acc0.w = fmaf(a0.w, wj, acc0.w);
            acc1.x = fmaf(a1.x, wj, acc1.x); acc1.y = fmaf(a1.y, wj, acc1.y);
            acc1.z = fmaf(a1.z, wj, acc1.z); acc1.w = fmaf(a1.w, wj, acc1.w);
        }
    }
    float denom = warp_sum(wlocal) + 1e-6f;
    float inv = 1.f / denom;

    const float4* ns4 = (const float4*)&nsin[(size_t)n * HH];
    float4 r0 = ns4[lane], r1 = ns4[32 + lane];
    float x[8];
    x[0] = fmaf(acc0.x, inv, r0.x); x[1] = fmaf(acc0.y, inv, r0.y);
    x[2] = fmaf(acc0.z, inv, r0.z); x[3] = fmaf(acc0.w, inv, r0.w);
    x[4] = fmaf(acc1.x, inv, r1.x); x[5] = fmaf(acc1.y, inv, r1.y);
    x[6] = fmaf(acc1.z, inv, r1.z); x[7] = fmaf(acc1.w, inv, r1.w);

    float lsum = ((x[0] + x[1]) + (x[2] + x[3])) + ((x[4] + x[5]) + (x[6] + x[7]));
    float m = warp_sum(lsum) * (1.f / HH);
    float vsum = 0.f;
#pragma unroll
    for (int i = 0; i < 8; i++) {
        float d = x[i] - m;
        vsum = fmaf(d, d, vsum);
    }
    float var = warp_sum(vsum) * (1.f / HH);
    float rs = rsqrtf(var + 1e-5f);

    const float4* gg = (const float4*)&gamma[0];
    const float4* bb = (const float4*)&beta[0];
    float4 g0 = gg[lane], g1 = gg[32 + lane];
    float4 b0 = bb[lane], b1 = bb[32 + lane];
    float gam[8] = {g0.x, g0.y, g0.z, g0.w, g1.x, g1.y, g1.z, g1.w};
    float bet[8] = {b0.x, b0.y, b0.z, b0.w, b1.x, b1.y, b1.z, b1.w};
    float o[8];
#pragma unroll
    for (int i = 0; i < 8; i++) {
        float y = fmaf((x[i] - m) * rs, gam[i], bet[i]);
        o[i] = 0.5f * y * (1.f + erff(y * 0.70710678118654752440f));
    }
    float4* out4 = (float4*)&nsout[(size_t)n * HH];
    out4[lane] = make_float4(o[0], o[1], o[2], o[3]);
    out4[32 + lane] = make_float4(o[4], o[5], o[6], o[7]);
}

// ---------------- pooling ----------------
// exact softmax without max shift: tanh-bounded scores, |s| <= sum|score_w| -> exp safe
__global__ void pool_exp_kernel(const int* __restrict__ node_ids) {
    int i = blockIdx.x * blockDim.x + threadIdx.x;
    float e = 0.f;
    if (i < NN) {
        if (node_ids[i] != 0) e = expf(g_sp[i]);
        g_bv[i] = e;
    }
    float r = blk_sum(e);
    if (threadIdx.x == 0) atomicAdd(&g_pool_sum, r);
}

#define FCHUNK 64
__global__ __launch_bounds__(HH) void final_kernel(const float* __restrict__ ns, float* __restrict__ out) {
    int base = blockIdx.x * FCHUNK;
    int tid = threadIdx.x;
    float sum = g_pool_sum;
    float inv = (sum > 0.f) ? 1.f / sum : 0.f;
    if (tid < FCHUNK) {
        int n = base + tid;
        if (n < NN) out[HH + n] = g_bv[n] * inv;
    }
    int lim = min(FCHUNK, NN - base);
    float a0 = 0.f, a1 = 0.f, a2 = 0.f, a3 = 0.f;
    int i = 0;
    for (; i + 4 <= lim; i += 4) {
        float w0 = g_bv[base + i] * inv,     w1 = g_bv[base + i + 1] * inv;
        float w2 = g_bv[base + i + 2] * inv, w3 = g_bv[base + i + 3] * inv;
        float h0 = ns[(size_t)(base + i) * HH + tid];
        float h1 = ns[(size_t)(base + i + 1) * HH + tid];
        float h2 = ns[(size_t)(base + i + 2) * HH + tid];
        float h3 = ns[(size_t)(base + i + 3) * HH + tid];
        a0 = fmaf(w0, h0, a0); a1 = fmaf(w1, h1, a1);
        a2 = fmaf(w2, h2, a2); a3 = fmaf(w3, h3, a3);
    }
    for (; i < lim; i++)
        a0 = fmaf(g_bv[base + i] * inv, ns[(size_t)(base + i) * HH + tid], a0);
    atomicAdd(&out[tid], (a0 + a1) + (a2 + a3));
}

// ---------------- launcher (single stream, no device-state mutation) ----------------
extern "C" void kernel_launch(void* const* d_in, const int* in_sizes, int n_in,
                              void* d_out, int out_size) {
    const int*   node_ids = (const int*)d_in[0];
    const int*   edge_index = (const int*)d_in[1];
    const float* emb    = (const float*)d_in[2];
    const float* proj_w = (const float*)d_in[3];
    const float* edge_w = (const float*)d_in[4];
    const float* ln_g   = (const float*)d_in[5];
    const float* ln_b   = (const float*)d_in[6];
    const float* pool_w = (const float*)d_in[7];
    const float* pool_b = (const float*)d_in[8];
    const float* score_w = (const float*)d_in[9];
    float* out = (float*)d_out;
    const int* src = edge_index;
    const int* dst = edge_index + EE;

    float *p_ns, *p_ns2, *p_h, *p_a0, *p_b0, *p_a1, *p_b1, *p_sp;
    cudaGetSymbolAddress((void**)&p_ns, g_ns);
    cudaGetSymbolAddress((void**)&p_ns2, g_ns2);
    cudaGetSymbolAddress((void**)&p_h, g_h);
    cudaGetSymbolAddress((void**)&p_a0, g_a0);
    cudaGetSymbolAddress((void**)&p_b0, g_b0);
    cudaGetSymbolAddress((void**)&p_a1, g_a1);
    cudaGetSymbolAddress((void**)&p_b1, g_b1);
    cudaGetSymbolAddress((void**)&p_sp, g_sp);

    dim3 gemm_grid((NN + 127) / 128, 2);
    int wpn_grid = (NN + 7) / 8;

    init_kernel<<<(NN + 255) / 256, 256>>>(out);                                  // 1
    deg_kernel<<<(EE + 255) / 256, 256>>>(dst);                                   // 2
    embed_kernel<<<NN, HH>>>(node_ids, emb);                                      // 3
    sgemm_mma<0><<<gemm_grid, 256>>>(p_ns, proj_w, p_h, NN,                       // 4 (profiled)
                                     edge_w, edge_w + HH, p_a0, p_b0);
    scan_kernel<<<1, 1024>>>();                                                   // 5
    scatter_kernel<<<(EE + 255) / 256, 256>>>(src, dst);                          // 6
    agg_kernel<<<wpn_grid, 256>>>(p_h, p_ns, p_ns2, ln_g, ln_b, p_a0, p_b0);      // 7

    // layer 1
    sgemm_mma<0><<<gemm_grid, 256>>>(p_ns2, proj_w + HH * HH, p_h, NN,
                                     edge_w + 2 * HH, edge_w + 3 * HH, p_a1, p_b1);
    agg_kernel<<<wpn_grid, 256>>>(p_h, p_ns2, p_ns, ln_g + HH, ln_b + HH, p_a1, p_b1);

    // pooling: GEMM with fused tanh/score epilogue (no C write)
    sgemm_mma<1><<<gemm_grid, 256>>>(p_ns, pool_w, p_h, NN, pool_b, score_w, p_sp, nullptr);
    pool_exp_kernel<<<(NN + 255) / 256, 256>>>(node_ids);
    final_kernel<<<(NN + FCHUNK - 1) / FCHUNK, HH>>>(p_ns, out);
}

// round 14
// speedup vs baseline: 2.4069x; 1.0088x over previous
#include <cuda_runtime.h>
#include <cuda_bf16.h>
#include <math.h>
#include <stdint.h>

#define NN 20000
#define HH 256
#define EE 320000

// ---------------- scratch (device globals; no allocation allowed) ----------------
__device__ float g_ns[(size_t)NN * HH];
__device__ float g_ns2[(size_t)NN * HH];
__device__ float g_h[(size_t)NN * HH];
__device__ float g_a0[NN], g_b0[NN];   // layer0 edge-score halves
__device__ float g_a1[NN], g_b1[NN];   // layer1 edge-score halves
__device__ float g_sp[NN];             // pooling scores
__device__ float g_bv[NN];             // pooling exp weights
__device__ int   g_deg[NN];
__device__ int   g_rowptr[NN + 1];
__device__ int   g_cursor[NN];
__device__ int   g_src_s[EE];
__device__ float g_pool_sum;

__device__ __forceinline__ float blk_sum(float v) {
    __shared__ float sh[32];
    int lane = threadIdx.x & 31, w = threadIdx.x >> 5;
#pragma unroll
    for (int o = 16; o; o >>= 1) v += __shfl_down_sync(0xffffffffu, v, o);
    if (!lane) sh[w] = v;
    __syncthreads();
    int nw = blockDim.x >> 5;
    float r = (threadIdx.x < nw) ? sh[threadIdx.x] : 0.f;
    if (w == 0) {
#pragma unroll
        for (int o = 16; o; o >>= 1) r += __shfl_down_sync(0xffffffffu, r, o);
        if (!lane) sh[0] = r;
    }
    __syncthreads();
    r = sh[0];
    __syncthreads();
    return r;
}

__device__ __forceinline__ float warp_sum(float v) {
#pragma unroll
    for (int o = 16; o; o >>= 1) v += __shfl_xor_sync(0xffffffffu, v, o);
    return v;
}

// ---------------- setup kernels ----------------
__global__ void init_kernel(float* out) {
    int i = blockIdx.x * blockDim.x + threadIdx.x;
    if (i < NN) {
        g_deg[i] = 0;
        g_a0[i] = 0.f; g_b0[i] = 0.f;
        g_a1[i] = 0.f; g_b1[i] = 0.f;
        g_sp[i] = 0.f;
    }
    if (i < HH) out[i] = 0.f;
    if (i == 0) g_pool_sum = 0.f;
}

__global__ void deg_kernel(const int* __restrict__ dst) {
    int e = blockIdx.x * blockDim.x + threadIdx.x;
    if (e < EE) atomicAdd(&g_deg[dst[e]], 1);
}

__global__ void scan_kernel() {
    __shared__ int ssum[1024];
    const int CH = (NN + 1023) / 1024; // 20
    int tid = threadIdx.x;
    int start = tid * CH;
    int local[32];
    int s = 0;
#pragma unroll
    for (int i = 0; i < CH; i++) {
        int idx = start + i;
        int d = (idx < NN) ? g_deg[idx] : 0;
        local[i] = s;
        s += d;
    }
    ssum[tid] = s;
    __syncthreads();
    for (int off = 1; off < 1024; off <<= 1) {
        int v = 0;
        if (tid >= off) v = ssum[tid - off];
        __syncthreads();
        if (tid >= off) ssum[tid] += v;
        __syncthreads();
    }
    int prefix = ssum[tid] - s;
#pragma unroll
    for (int i = 0; i < CH; i++) {
        int idx = start + i;
        if (idx < NN) {
            int p = prefix + local[i];
            g_rowptr[idx] = p;
            g_cursor[idx] = p;
        }
    }
    if (tid == 1023) g_rowptr[NN] = ssum[1023];
}

__global__ void scatter_kernel(const int* __restrict__ src, const int* __restrict__ dst) {
    int e = blockIdx.x * blockDim.x + threadIdx.x;
    if (e < EE) {
        int d = dst[e];
        int pos = atomicAdd(&g_cursor[d], 1);
        g_src_s[pos] = src[e];
    }
}

__global__ void embed_kernel(const int* __restrict__ node_ids, const float* __restrict__ emb) {
    int n = blockIdx.x;
    int t = threadIdx.x;
    g_ns[(size_t)n * HH + t] = emb[(size_t)node_ids[n] * HH + t];
}

// ---------------- TF32 mma.sync SGEMM, 2-stage cp.async, CTA 64x128, fused epilogues ----
// C[M,256] = A[M,256] * B[256,256]^T. CTA 64x128, BK=16, 8 warps (2m x 4n),
// warp tile 32x32 of m16n8k8, 3 CTAs/SM target. Raw f32 fed to tf32 mma.
// MODE 0: write C and accumulate a[row]=C[row]·w1, b[row]=C[row]·w2 (edge MLP halves).
// MODE 1: no C write; accumulate s[row]=sum(tanh(C[row]+w1)*w2) (attention pooling).
#define SPAD 20
#define TM 64
#define TN 128

__device__ __forceinline__ void mma_tf32(float* c, const uint32_t* a, const uint32_t* b) {
    asm volatile(
        "mma.sync.aligned.m16n8k8.row.col.f32.tf32.tf32.f32 "
        "{%0,%1,%2,%3}, {%4,%5,%6,%7}, {%8,%9}, {%0,%1,%2,%3};"
        : "+f"(c[0]), "+f"(c[1]), "+f"(c[2]), "+f"(c[3])
        : "r"(a[0]), "r"(a[1]), "r"(a[2]), "r"(a[3]), "r"(b[0]), "r"(b[1]));
}

__device__ __forceinline__ void cp16(float* smem_dst, const float* gsrc, bool valid) {
    uint32_t s = (uint32_t)__cvta_generic_to_shared(smem_dst);
    int sz = valid ? 16 : 0;  // sz=0 -> 16B zero-fill
    asm volatile("cp.async.cg.shared.global [%0], [%1], 16, %2;"
                 :: "r"(s), "l"(gsrc), "r"(sz));
}

template <int MODE>
__global__ __launch_bounds__(256, 3) void sgemm_mma(const float* __restrict__ A,
                                                    const float* __restrict__ B,
                                                    float* __restrict__ C, int M,
                                                    const float* __restrict__ w1,
                                                    const float* __restrict__ w2,
                                                    float* __restrict__ accA,
                                                    float* __restrict__ accB) {
    __shared__ float As[2][TM * SPAD];
    __shared__ float Bs[2][TN * SPAD];
    const int tid = threadIdx.x;
    const int lane = tid & 31, w = tid >> 5;
    const int wm = w & 1, wn = w >> 1;     // warp grid 2 (m) x 4 (n)
    const int g = lane >> 2, t4 = lane & 3;
    const int bm = blockIdx.x * TM, bn = blockIdx.y * TN;

    float c[2][4][4];
#pragma unroll
    for (int mi = 0; mi < 2; mi++)
#pragma unroll
        for (int ni = 0; ni < 4; ni++)
#pragma unroll
            for (int j = 0; j < 4; j++) c[mi][ni][j] = 0.f;

    const int r0 = tid >> 2, q0 = tid & 3; // 64 rows x 4 quads = 256 slots
    const int ga0 = bm + r0;
    const bool v0 = ga0 < M;
    const float* pA0 = &A[(size_t)(v0 ? ga0 : 0) * HH + q0 * 4];
    const float* pB0 = &B[(size_t)(bn + r0) * HH + q0 * 4];
    const float* pB1 = &B[(size_t)(bn + r0 + 64) * HH + q0 * 4];
    float* sA0 = &As[0][r0 * SPAD + q0 * 4];
    float* sB0 = &Bs[0][r0 * SPAD + q0 * 4];
    float* sB1 = &Bs[0][(r0 + 64) * SPAD + q0 * 4];
    const int SA = TM * SPAD, SB = TN * SPAD;

    // prologue: issue k-tile 0 into buffer 0
    cp16(sA0, pA0, v0);
    cp16(sB0, pB0, true);
    cp16(sB1, pB1, true);
    asm volatile("cp.async.commit_group;" ::: "memory");

#pragma unroll 1
    for (int it = 0; it < 16; it++) {
        asm volatile("cp.async.wait_group 0;" ::: "memory");
        __syncthreads();
        const int st = it & 1;
        if (it < 15) {
            const int nst = (it + 1) & 1;
            const int k0 = (it + 1) * 16;
            cp16(sA0 + nst * SA, pA0 + k0, v0);
            cp16(sB0 + nst * SB, pB0 + k0, true);
            cp16(sB1 + nst * SB, pB1 + k0, true);
            asm volatile("cp.async.commit_group;" ::: "memory");
        }
        const uint32_t* Asb = (const uint32_t*)&As[st][0];
        const uint32_t* Bsb = (const uint32_t*)&Bs[st][0];
#pragma unroll
        for (int ks = 0; ks < 2; ks++) {
            const int kb = ks * 8 + t4;
            uint32_t af[2][4];
#pragma unroll
            for (int mi = 0; mi < 2; mi++) {
                const int rr = wm * 32 + mi * 16 + g;
                af[mi][0] = Asb[rr * SPAD + kb];
                af[mi][1] = Asb[(rr + 8) * SPAD + kb];
                af[mi][2] = Asb[rr * SPAD + kb + 4];
                af[mi][3] = Asb[(rr + 8) * SPAD + kb + 4];
            }
            uint32_t bf[4][2];
#pragma unroll
            for (int ni = 0; ni < 4; ni++) {
                const int cc = wn * 32 + ni * 8 + g;
                bf[ni][0] = Bsb[cc * SPAD + kb];
                bf[ni][1] = Bsb[cc * SPAD + kb + 4];
            }
#pragma unroll
            for (int mi = 0; mi < 2; mi++)
#pragma unroll
                for (int ni = 0; ni < 4; ni++)
                    mma_tf32(c[mi][ni], af[mi], bf[ni]);
        }
        __syncthreads();
    }

    // epilogue: C write (MODE 0) + fused row reductions
#pragma unroll
    for (int mi = 0; mi < 2; mi++) {
        const int row = bm + wm * 32 + mi * 16 + g;
        float palo = 0.f, pahi = 0.f, pblo = 0.f, pbhi = 0.f;
#pragma unroll
        for (int ni = 0; ni < 4; ni++) {
            const int col = bn + wn * 32 + ni * 8 + 2 * t4;
            if (MODE == 0) {
                const float e0 = __ldg(&w1[col]), e1 = __ldg(&w1[col + 1]);
                const float f0 = __ldg(&w2[col]), f1 = __ldg(&w2[col + 1]);
                palo += c[mi][ni][0] * e0 + c[mi][ni][1] * e1;
                pahi += c[mi][ni][2] * e0 + c[mi][ni][3] * e1;
                pblo += c[mi][ni][0] * f0 + c[mi][ni][1] * f1;
                pbhi += c[mi][ni][2] * f0 + c[mi][ni][3] * f1;
                if (row < M)
                    *(float2*)&C[(size_t)row * HH + col] = make_float2(c[mi][ni][0], c[mi][ni][1]);
                if (row + 8 < M)
                    *(float2*)&C[(size_t)(row + 8) * HH + col] = make_float2(c[mi][ni][2], c[mi][ni][3]);
            } else {
                const float p0 = __ldg(&w1[col]), p1 = __ldg(&w1[col + 1]);
                const float s0 = __ldg(&w2[col]), s1 = __ldg(&w2[col + 1]);
                palo += tanhf(c[mi][ni][0] + p0) * s0 + tanhf(c[mi][ni][1] + p1) * s1;
                pahi += tanhf(c[mi][ni][2] + p0) * s0 + tanhf(c[mi][ni][3] + p1) * s1;
            }
        }
        palo += __shfl_xor_sync(0xffffffffu, palo, 1);
        palo += __shfl_xor_sync(0xffffffffu, palo, 2);
        pahi += __shfl_xor_sync(0xffffffffu, pahi, 1);
        pahi += __shfl_xor_sync(0xffffffffu, pahi, 2);
        if (MODE == 0) {
            pblo += __shfl_xor_sync(0xffffffffu, pblo, 1);
            pblo += __shfl_xor_sync(0xffffffffu, pblo, 2);
            pbhi += __shfl_xor_sync(0xffffffffu, pbhi, 1);
            pbhi += __shfl_xor_sync(0xffffffffu, pbhi, 2);
        }
        if (t4 == 0) {
            if (row < M) {
                atomicAdd(&accA[row], palo);
                if (MODE == 0) atomicAdd(&accB[row], pblo);
            }
            if (row + 8 < M) {
                atomicAdd(&accA[row + 8], pahi);
                if (MODE == 0) atomicAdd(&accB[row + 8], pbhi);
            }
        }
    }
}

// ---------------- per-layer kernels ----------------
// warp-per-node fused aggregation: inline softmax weights (global max cancels
// up to the +1e-6 term, ~1e-7 relative), weighted gather-sum, residual, LN, GELU.
__global__ __launch_bounds__(256) void agg_kernel(const float* __restrict__ hbuf,
                                                  const float* __restrict__ nsin,
                                                  float* __restrict__ nsout,
                                                  const float* __restrict__ gamma,
                                                  const float* __restrict__ beta,
                                                  const float* __restrict__ av,
                                                  const float* __restrict__ bv) {
    int wid = threadIdx.x >> 5, lane = threadIdx.x & 31;
    int n = blockIdx.x * 8 + wid;
    if (n >= NN) return;
    int beg = g_rowptr[n], end = g_rowptr[n + 1];
    float bvn = bv[n];

    float4 acc0 = make_float4(0.f, 0.f, 0.f, 0.f);
    float4 acc1 = make_float4(0.f, 0.f, 0.f, 0.f);
    float wlocal = 0.f;

    for (int base = beg; base < end; base += 32) {
        int cnt = min(32, end - base);
        int sv = 0;
        float wv = 0.f;
        if (lane < cnt) {
            sv = g_src_s[base + lane];
            float sc = av[sv] + bvn;
            sc = (sc >= 0.f) ? sc : 0.2f * sc;
            wv = expf(sc);
        }
        wlocal += wv;
        int j = 0;
        for (; j + 2 <= cnt; j += 2) {
            int   sj0 = __shfl_sync(0xffffffffu, sv, j);
            int   sj1 = __shfl_sync(0xffffffffu, sv, j + 1);
            float wj0 = __shfl_sync(0xffffffffu, wv, j);
            float wj1 = __shfl_sync(0xffffffffu, wv, j + 1);
            const float4* ra = (const float4*)&hbuf[(size_t)sj0 * HH];
            const float4* rb = (const float4*)&hbuf[(size_t)sj1 * HH];
            float4 a0 = ra[lane], a1 = ra[32 + lane];
            float4 b0 = rb[lane], b1 = rb[32 + lane];
            acc0.x = fmaf(a0.x, wj0, acc0.x); acc0.y = fmaf(a0.y, wj0, acc0.y);
            acc0.z = fmaf(a0.z, wj0, acc0.z); acc0.w = fmaf(a0.w, wj0, acc0.w);
            acc1.x = fmaf(a1.x, wj0, acc1.x); acc1.y = fmaf(a1.y, wj0, acc1.y);
            acc1.z = fmaf(a1.z, wj0, acc1.z); acc1.w = fmaf(a1.w, wj0, acc1.w);
            acc0.x = fmaf(b0.x, wj1, acc0.x); acc0.y = fmaf(b0.y, wj1, acc0.y);
            acc0.z = fmaf(b0.z, wj1, acc0.z); acc0.w = fmaf(b0.w, wj1, acc0.w);
            acc1.x = fmaf(b1.x, wj1, acc1.x); acc1.y = fmaf(b1.y, wj1, acc1.y);
            acc1.z = fmaf(b1.z, wj1, acc1.z); acc1.w = fmaf(b1.w, wj1, acc1.w);
        }
        if (j < cnt) {
            int   sj = __shfl_sync(0xffffffffu, sv, j);
            float wj = __shfl_sync(0xffffffffu, wv, j);
            const float4* ra = (const float4*)&hbuf[(size_t)sj * HH];
            float4 a0 = ra[lane], a1 = ra[32 + lane];
            acc0.x = fmaf(a0.x, wj, acc0.x); acc0.y = fmaf(a0.y, wj, acc0.y);
            acc0.z = fmaf(a0.z, wj, acc0.z); acc0.w = fmaf(a0.w, wj, acc0.w);
            acc1.x = fmaf(a1.x, wj, acc1.x); acc1.y = fmaf(a1.y, wj, acc1.y);
            acc1.z = fmaf(a1.z, wj, acc1.z); acc1.w = fmaf(a1.w, wj, acc1.w);
        }
    }
    float denom = warp_sum(wlocal) + 1e-6f;
    float inv = 1.f / denom;

    const float4* ns4 = (const float4*)&nsin[(size_t)n * HH];
    float4 r0 = ns4[lane], r1 = ns4[32 + lane];
    float x[8];
    x[0] = fmaf(acc0.x, inv, r0.x); x[1] = fmaf(acc0.y, inv, r0.y);
    x[2] = fmaf(acc0.z, inv, r0.z); x[3] = fmaf(acc0.w, inv, r0.w);
    x[4] = fmaf(acc1.x, inv, r1.x); x[5] = fmaf(acc1.y, inv, r1.y);
    x[6] = fmaf(acc1.z, inv, r1.z); x[7] = fmaf(acc1.w, inv, r1.w);

    float lsum = ((x[0] + x[1]) + (x[2] + x[3])) + ((x[4] + x[5]) + (x[6] + x[7]));
    float m = warp_sum(lsum) * (1.f / HH);
    float vsum = 0.f;
#pragma unroll
    for (int i = 0; i < 8; i++) {
        float d = x[i] - m;
        vsum = fmaf(d, d, vsum);
    }
    float var = warp_sum(vsum) * (1.f / HH);
    float rs = rsqrtf(var + 1e-5f);

    const float4* gg = (const float4*)&gamma[0];
    const float4* bb = (const float4*)&beta[0];
    float4 g0 = gg[lane], g1 = gg[32 + lane];
    float4 b0 = bb[lane], b1 = bb[32 + lane];
    float gam[8] = {g0.x, g0.y, g0.z, g0.w, g1.x, g1.y, g1.z, g1.w};
    float bet[8] = {b0.x, b0.y, b0.z, b0.w, b1.x, b1.y, b1.z, b1.w};
    float o[8];
#pragma unroll
    for (int i = 0; i < 8; i++) {
        float y = fmaf((x[i] - m) * rs, gam[i], bet[i]);
        o[i] = 0.5f * y * (1.f + erff(y * 0.70710678118654752440f));
    }
    float4* out4 = (float4*)&nsout[(size_t)n * HH];
    out4[lane] = make_float4(o[0], o[1], o[2], o[3]);
    out4[32 + lane] = make_float4(o[4], o[5], o[6], o[7]);
}

// ---------------- pooling ----------------
// exact softmax without max shift: tanh-bounded scores, |s| <= sum|score_w| -> exp safe
__global__ void pool_exp_kernel(const int* __restrict__ node_ids) {
    int i = blockIdx.x * blockDim.x + threadIdx.x;
    float e = 0.f;
    if (i < NN) {
        if (node_ids[i] != 0) e = expf(g_sp[i]);
        g_bv[i] = e;
    }
    float r = blk_sum(e);
    if (threadIdx.x == 0) atomicAdd(&g_pool_sum, r);
}

#define FCHUNK 64
__global__ __launch_bounds__(HH) void final_kernel(const float* __restrict__ ns, float* __restrict__ out) {
    int base = blockIdx.x * FCHUNK;
    int tid = threadIdx.x;
    float sum = g_pool_sum;
    float inv = (sum > 0.f) ? 1.f / sum : 0.f;
    if (tid < FCHUNK) {
        int n = base + tid;
        if (n < NN) out[HH + n] = g_bv[n] * inv;
    }
    int lim = min(FCHUNK, NN - base);
    float a0 = 0.f, a1 = 0.f, a2 = 0.f, a3 = 0.f;
    int i = 0;
    for (; i + 4 <= lim; i += 4) {
        float w0 = g_bv[base + i] * inv,     w1 = g_bv[base + i + 1] * inv;
        float w2 = g_bv[base + i + 2] * inv, w3 = g_bv[base + i + 3] * inv;
        float h0 = ns[(size_t)(base + i) * HH + tid];
        float h1 = ns[(size_t)(base + i + 1) * HH + tid];
        float h2 = ns[(size_t)(base + i + 2) * HH + tid];
        float h3 = ns[(size_t)(base + i + 3) * HH + tid];
        a0 = fmaf(w0, h0, a0); a1 = fmaf(w1, h1, a1);
        a2 = fmaf(w2, h2, a2); a3 = fmaf(w3, h3, a3);
    }
    for (; i < lim; i++)
        a0 = fmaf(g_bv[base + i] * inv, ns[(size_t)(base + i) * HH + tid], a0);
    atomicAdd(&out[tid], (a0 + a1) + (a2 + a3));
}

// ---------------- launcher (single stream, no device-state mutation) ----------------
extern "C" void kernel_launch(void* const* d_in, const int* in_sizes, int n_in,
                              void* d_out, int out_size) {
    const int*   node_ids = (const int*)d_in[0];
    const int*   edge_index = (const int*)d_in[1];
    const float* emb    = (const float*)d_in[2];
    const float* proj_w = (const float*)d_in[3];
    const float* edge_w = (const float*)d_in[4];
    const float* ln_g   = (const float*)d_in[5];
    const float* ln_b   = (const float*)d_in[6];
    const float* pool_w = (const float*)d_in[7];
    const float* pool_b = (const float*)d_in[8];
    const float* score_w = (const float*)d_in[9];
    float* out = (float*)d_out;
    const int* src = edge_index;
    const int* dst = edge_index + EE;

    float *p_ns, *p_ns2, *p_h, *p_a0, *p_b0, *p_a1, *p_b1, *p_sp;
    cudaGetSymbolAddress((void**)&p_ns, g_ns);
    cudaGetSymbolAddress((void**)&p_ns2, g_ns2);
    cudaGetSymbolAddress((void**)&p_h, g_h);
    cudaGetSymbolAddress((void**)&p_a0, g_a0);
    cudaGetSymbolAddress((void**)&p_b0, g_b0);
    cudaGetSymbolAddress((void**)&p_a1, g_a1);
    cudaGetSymbolAddress((void**)&p_b1, g_b1);
    cudaGetSymbolAddress((void**)&p_sp, g_sp);

    dim3 gemm_grid((NN + TM - 1) / TM, HH / TN);
    int wpn_grid = (NN + 7) / 8;

    init_kernel<<<(NN + 255) / 256, 256>>>(out);                                  // 1
    deg_kernel<<<(EE + 255) / 256, 256>>>(dst);                                   // 2
    embed_kernel<<<NN, HH>>>(node_ids, emb);                                      // 3
    sgemm_mma<0><<<gemm_grid, 256>>>(p_ns, proj_w, p_h, NN,                       // 4 (profiled)
                                     edge_w, edge_w + HH, p_a0, p_b0);
    scan_kernel<<<1, 1024>>>();                                                   // 5
    scatter_kernel<<<(EE + 255) / 256, 256>>>(src, dst);                          // 6
    agg_kernel<<<wpn_grid, 256>>>(p_h, p_ns, p_ns2, ln_g, ln_b, p_a0, p_b0);      // 7

    // layer 1
    sgemm_mma<0><<<gemm_grid, 256>>>(p_ns2, proj_w + HH * HH, p_h, NN,
                                     edge_w + 2 * HH, edge_w + 3 * HH, p_a1, p_b1);
    agg_kernel<<<wpn_grid, 256>>>(p_h, p_ns2, p_ns, ln_g + HH, ln_b + HH, p_a1, p_b1);

    // pooling: GEMM with fused tanh/score epilogue (no C write)
    sgemm_mma<1><<<gemm_grid, 256>>>(p_ns, pool_w, p_h, NN, pool_b, score_w, p_sp, nullptr);
    pool_exp_kernel<<<(NN + 255) / 256, 256>>>(node_ids);
    final_kernel<<<(NN + FCHUNK - 1) / FCHUNK, HH>>>(p_ns, out);
}

// round 15
// speedup vs baseline: 2.4143x; 1.0031x over previous
#include <cuda_runtime.h>
#include <cuda_bf16.h>
#include <math.h>
#include <stdint.h>

#define NN 20000
#define HH 256
#define EE 320000

// ---------------- scratch (device globals; no allocation allowed) ----------------
__device__ float g_ns[(size_t)NN * HH];
__device__ float g_ns2[(size_t)NN * HH];
__device__ float g_h[(size_t)NN * HH];
__device__ float g_a0[NN], g_b0[NN];   // layer0 edge-score halves
__device__ float g_a1[NN], g_b1[NN];   // layer1 edge-score halves
__device__ float g_sp[NN];             // pooling scores
__device__ float g_bv[NN];             // pooling exp weights
__device__ int   g_deg[NN];
__device__ int   g_rowptr[NN + 1];
__device__ int   g_cursor[NN];
__device__ int   g_src_s[EE];
__device__ float g_pool_sum;

__device__ __forceinline__ float blk_sum(float v) {
    __shared__ float sh[32];
    int lane = threadIdx.x & 31, w = threadIdx.x >> 5;
#pragma unroll
    for (int o = 16; o; o >>= 1) v += __shfl_down_sync(0xffffffffu, v, o);
    if (!lane) sh[w] = v;
    __syncthreads();
    int nw = blockDim.x >> 5;
    float r = (threadIdx.x < nw) ? sh[threadIdx.x] : 0.f;
    if (w == 0) {
#pragma unroll
        for (int o = 16; o; o >>= 1) r += __shfl_down_sync(0xffffffffu, r, o);
        if (!lane) sh[0] = r;
    }
    __syncthreads();
    r = sh[0];
    __syncthreads();
    return r;
}

__device__ __forceinline__ float warp_sum(float v) {
#pragma unroll
    for (int o = 16; o; o >>= 1) v += __shfl_xor_sync(0xffffffffu, v, o);
    return v;
}

// ---------------- setup kernels ----------------
__global__ void init_kernel(float* out) {
    int i = blockIdx.x * blockDim.x + threadIdx.x;
    if (i < NN) {
        g_deg[i] = 0;
        g_a0[i] = 0.f; g_b0[i] = 0.f;
        g_a1[i] = 0.f; g_b1[i] = 0.f;
        g_sp[i] = 0.f;
    }
    if (i < HH) out[i] = 0.f;
    if (i == 0) g_pool_sum = 0.f;
}

__global__ void deg_kernel(const int* __restrict__ dst) {
    int e = blockIdx.x * blockDim.x + threadIdx.x;
    if (e < EE) atomicAdd(&g_deg[dst[e]], 1);
}

__global__ void scan_kernel() {
    __shared__ int ssum[1024];
    const int CH = (NN + 1023) / 1024; // 20
    int tid = threadIdx.x;
    int start = tid * CH;
    int local[32];
    int s = 0;
#pragma unroll
    for (int i = 0; i < CH; i++) {
        int idx = start + i;
        int d = (idx < NN) ? g_deg[idx] : 0;
        local[i] = s;
        s += d;
    }
    ssum[tid] = s;
    __syncthreads();
    for (int off = 1; off < 1024; off <<= 1) {
        int v = 0;
        if (tid >= off) v = ssum[tid - off];
        __syncthreads();
        if (tid >= off) ssum[tid] += v;
        __syncthreads();
    }
    int prefix = ssum[tid] - s;
#pragma unroll
    for (int i = 0; i < CH; i++) {
        int idx = start + i;
        if (idx < NN) {
            int p = prefix + local[i];
            g_rowptr[idx] = p;
            g_cursor[idx] = p;
        }
    }
    if (tid == 1023) g_rowptr[NN] = ssum[1023];
}

__global__ void scatter_kernel(const int* __restrict__ src, const int* __restrict__ dst) {
    int e = blockIdx.x * blockDim.x + threadIdx.x;
    if (e < EE) {
        int d = dst[e];
        int pos = atomicAdd(&g_cursor[d], 1);
        g_src_s[pos] = src[e];
    }
}

__global__ void embed_kernel(const int* __restrict__ node_ids, const float* __restrict__ emb) {
    int n = blockIdx.x;
    int t = threadIdx.x;
    g_ns[(size_t)n * HH + t] = emb[(size_t)node_ids[n] * HH + t];
}

// ---------------- TF32 mma.sync SGEMM, 3-stage cp.async (static 46KB), fused epilogues ----
// C[M,256] = A[M,256] * B[256,256]^T. CTA 64x128, BK=16, 8 warps (2m x 4n),
// warp tile 32x32 of m16n8k8. Raw f32 fed to tf32 mma (HW truncation).
// 3-stage ring, prefetch distance 2, ONE barrier per k-iteration.
// MODE 0: write C and accumulate a[row]=C[row]·w1, b[row]=C[row]·w2 (edge MLP halves).
// MODE 1: no C write; accumulate s[row]=sum(tanh(C[row]+w1)*w2) (attention pooling).
#define SPAD 20
#define TM 64
#define TN 128

__device__ __forceinline__ void mma_tf32(float* c, const uint32_t* a, const uint32_t* b) {
    asm volatile(
        "mma.sync.aligned.m16n8k8.row.col.f32.tf32.tf32.f32 "
        "{%0,%1,%2,%3}, {%4,%5,%6,%7}, {%8,%9}, {%0,%1,%2,%3};"
        : "+f"(c[0]), "+f"(c[1]), "+f"(c[2]), "+f"(c[3])
        : "r"(a[0]), "r"(a[1]), "r"(a[2]), "r"(a[3]), "r"(b[0]), "r"(b[1]));
}

__device__ __forceinline__ void cp16(float* smem_dst, const float* gsrc, bool valid) {
    uint32_t s = (uint32_t)__cvta_generic_to_shared(smem_dst);
    int sz = valid ? 16 : 0;  // sz=0 -> 16B zero-fill
    asm volatile("cp.async.cg.shared.global [%0], [%1], 16, %2;"
                 :: "r"(s), "l"(gsrc), "r"(sz));
}

template <int MODE>
__global__ __launch_bounds__(256, 3) void sgemm_mma(const float* __restrict__ A,
                                                    const float* __restrict__ B,
                                                    float* __restrict__ C, int M,
                                                    const float* __restrict__ w1,
                                                    const float* __restrict__ w2,
                                                    float* __restrict__ accA,
                                                    float* __restrict__ accB) {
    __shared__ float As[3][TM * SPAD];   // 15360 B
    __shared__ float Bs[3][TN * SPAD];   // 30720 B  (total 46080 B < 48 KB)
    const int tid = threadIdx.x;
    const int lane = tid & 31, w = tid >> 5;
    const int wm = w & 1, wn = w >> 1;     // warp grid 2 (m) x 4 (n)
    const int g = lane >> 2, t4 = lane & 3;
    const int bm = blockIdx.x * TM, bn = blockIdx.y * TN;

    float c[2][4][4];
#pragma unroll
    for (int mi = 0; mi < 2; mi++)
#pragma unroll
        for (int ni = 0; ni < 4; ni++)
#pragma unroll
            for (int j = 0; j < 4; j++) c[mi][ni][j] = 0.f;

    const int r0 = tid >> 2, q0 = tid & 3; // 64 rows x 4 quads = 256 slots
    const int ga0 = bm + r0;
    const bool v0 = ga0 < M;
    const float* pA0 = &A[(size_t)(v0 ? ga0 : 0) * HH + q0 * 4];
    const float* pB0 = &B[(size_t)(bn + r0) * HH + q0 * 4];
    const float* pB1 = &B[(size_t)(bn + r0 + 64) * HH + q0 * 4];
    const int soA = r0 * SPAD + q0 * 4;
    const int soB0 = r0 * SPAD + q0 * 4;
    const int soB1 = (r0 + 64) * SPAD + q0 * 4;

    // prologue: issue k-tiles 0 and 1 into stages 0 and 1
#pragma unroll
    for (int t = 0; t < 2; t++) {
        const int k0 = t * 16;
        cp16(&As[t][soA], pA0 + k0, v0);
        cp16(&Bs[t][soB0], pB0 + k0, true);
        cp16(&Bs[t][soB1], pB1 + k0, true);
        asm volatile("cp.async.commit_group;" ::: "memory");
    }

#pragma unroll 1
    for (int it = 0; it < 16; it++) {
        if (it < 15)
            asm volatile("cp.async.wait_group 1;" ::: "memory");
        else
            asm volatile("cp.async.wait_group 0;" ::: "memory");
        __syncthreads();   // also guarantees stage (it+2)%3 == (it-1)%3 is compute-done
        if (it + 2 < 16) {
            const int st2 = (it + 2) % 3;
            const int k0 = (it + 2) * 16;
            cp16(&As[st2][soA], pA0 + k0, v0);
            cp16(&Bs[st2][soB0], pB0 + k0, true);
            cp16(&Bs[st2][soB1], pB1 + k0, true);
            asm volatile("cp.async.commit_group;" ::: "memory");
        }
        const int st = it % 3;
        const uint32_t* Asb = (const uint32_t*)&As[st][0];
        const uint32_t* Bsb = (const uint32_t*)&Bs[st][0];
#pragma unroll
        for (int ks = 0; ks < 2; ks++) {
            const int kb = ks * 8 + t4;
            uint32_t af[2][4];
#pragma unroll
            for (int mi = 0; mi < 2; mi++) {
                const int rr = wm * 32 + mi * 16 + g;
                af[mi][0] = Asb[rr * SPAD + kb];
                af[mi][1] = Asb[(rr + 8) * SPAD + kb];
                af[mi][2] = Asb[rr * SPAD + kb + 4];
                af[mi][3] = Asb[(rr + 8) * SPAD + kb + 4];
            }
            uint32_t bf[4][2];
#pragma unroll
            for (int ni = 0; ni < 4; ni++) {
                const int cc = wn * 32 + ni * 8 + g;
                bf[ni][0] = Bsb[cc * SPAD + kb];
                bf[ni][1] = Bsb[cc * SPAD + kb + 4];
            }
#pragma unroll
            for (int mi = 0; mi < 2; mi++)
#pragma unroll
                for (int ni = 0; ni < 4; ni++)
                    mma_tf32(c[mi][ni], af[mi], bf[ni]);
        }
    }

    // epilogue: C write (MODE 0) + fused row reductions
#pragma unroll
    for (int mi = 0; mi < 2; mi++) {
        const int row = bm + wm * 32 + mi * 16 + g;
        float palo = 0.f, pahi = 0.f, pblo = 0.f, pbhi = 0.f;
#pragma unroll
        for (int ni = 0; ni < 4; ni++) {
            const int col = bn + wn * 32 + ni * 8 + 2 * t4;
            if (MODE == 0) {
                const float e0 = __ldg(&w1[col]), e1 = __ldg(&w1[col + 1]);
                const float f0 = __ldg(&w2[col]), f1 = __ldg(&w2[col + 1]);
                palo += c[mi][ni][0] * e0 + c[mi][ni][1] * e1;
                pahi += c[mi][ni][2] * e0 + c[mi][ni][3] * e1;
                pblo += c[mi][ni][0] * f0 + c[mi][ni][1] * f1;
                pbhi += c[mi][ni][2] * f0 + c[mi][ni][3] * f1;
                if (row < M)
                    *(float2*)&C[(size_t)row * HH + col] = make_float2(c[mi][ni][0], c[mi][ni][1]);
                if (row + 8 < M)
                    *(float2*)&C[(size_t)(row + 8) * HH + col] = make_float2(c[mi][ni][2], c[mi][ni][3]);
            } else {
                const float p0 = __ldg(&w1[col]), p1 = __ldg(&w1[col + 1]);
                const float s0 = __ldg(&w2[col]), s1 = __ldg(&w2[col + 1]);
                palo += tanhf(c[mi][ni][0] + p0) * s0 + tanhf(c[mi][ni][1] + p1) * s1;
                pahi += tanhf(c[mi][ni][2] + p0) * s0 + tanhf(c[mi][ni][3] + p1) * s1;
            }
        }
        palo += __shfl_xor_sync(0xffffffffu, palo, 1);
        palo += __shfl_xor_sync(0xffffffffu, palo, 2);
        pahi += __shfl_xor_sync(0xffffffffu, pahi, 1);
        pahi += __shfl_xor_sync(0xffffffffu, pahi, 2);
        if (MODE == 0) {
            pblo += __shfl_xor_sync(0xffffffffu, pblo, 1);
            pblo += __shfl_xor_sync(0xffffffffu, pblo, 2);
            pbhi += __shfl_xor_sync(0xffffffffu, pbhi, 1);
            pbhi += __shfl_xor_sync(0xffffffffu, pbhi, 2);
        }
        if (t4 == 0) {
            if (row < M) {
                atomicAdd(&accA[row], palo);
                if (MODE == 0) atomicAdd(&accB[row], pblo);
            }
            if (row + 8 < M) {
                atomicAdd(&accA[row + 8], pahi);
                if (MODE == 0) atomicAdd(&accB[row + 8], pbhi);
            }
        }
    }
}

// ---------------- per-layer kernels ----------------
// warp-per-node fused aggregation: inline softmax weights (global max cancels
// up to the +1e-6 term, ~1e-7 relative), weighted gather-sum, residual, LN, GELU.
__global__ __launch_bounds__(256) void agg_kernel(const float* __restrict__ hbuf,
                                                  const float* __restrict__ nsin,
                                                  float* __restrict__ nsout,
                                                  const float* __restrict__ gamma,
                                                  const float* __restrict__ beta,
                                                  const float* __restrict__ av,
                                                  const float* __restrict__ bv) {
    int wid = threadIdx.x >> 5, lane = threadIdx.x & 31;
    int n = blockIdx.x * 8 + wid;
    if (n >= NN) return;
    int beg = g_rowptr[n], end = g_rowptr[n + 1];
    float bvn = bv[n];

    float4 acc0 = make_float4(0.f, 0.f, 0.f, 0.f);
    float4 acc1 = make_float4(0.f, 0.f, 0.f, 0.f);
    float wlocal = 0.f;

    for (int base = beg; base < end; base += 32) {
        int cnt = min(32, end - base);
        int sv = 0;
        float wv = 0.f;
        if (lane < cnt) {
            sv = g_src_s[base + lane];
            float sc = av[sv] + bvn;
            sc = (sc >= 0.f) ? sc : 0.2f * sc;
            wv = expf(sc);
        }
        wlocal += wv;
        int j = 0;
        for (; j + 2 <= cnt; j += 2) {
            int   sj0 = __shfl_sync(0xffffffffu, sv, j);
            int   sj1 = __shfl_sync(0xffffffffu, sv, j + 1);
            float wj0 = __shfl_sync(0xffffffffu, wv, j);
            float wj1 = __shfl_sync(0xffffffffu, wv, j + 1);
            const float4* ra = (const float4*)&hbuf[(size_t)sj0 * HH];
            const float4* rb = (const float4*)&hbuf[(size_t)sj1 * HH];
            float4 a0 = ra[lane], a1 = ra[32 + lane];
            float4 b0 = rb[lane], b1 = rb[32 + lane];
            acc0.x = fmaf(a0.x, wj0, acc0.x); acc0.y = fmaf(a0.y, wj0, acc0.y);
            acc0.z = fmaf(a0.z, wj0, acc0.z); acc0.w = fmaf(a0.w, wj0, acc0.w);
            acc1.x = fmaf(a1.x, wj0, acc1.x); acc1.y = fmaf(a1.y, wj0, acc1.y);
            acc1.z = fmaf(a1.z, wj0, acc1.z); acc1.w = fmaf(a1.w, wj0, acc1.w);
            acc0.x = fmaf(b0.x, wj1, acc0.x); acc0.y = fmaf(b0.y, wj1, acc0.y);
            acc0.z = fmaf(b0.z, wj1, acc0.z); acc0.w = fmaf(b0.w, wj1, acc0.w);
            acc1.x = fmaf(b1.x, wj1, acc1.x); acc1.y = fmaf(b1.y, wj1, acc1.y);
            acc1.z = fmaf(b1.z, wj1, acc1.z); acc1.w = fmaf(b1.w, wj1, acc1.w);
        }
        if (j < cnt) {
            int   sj = __shfl_sync(0xffffffffu, sv, j);
            float wj = __shfl_sync(0xffffffffu, wv, j);
            const float4* ra = (const float4*)&hbuf[(size_t)sj * HH];
            float4 a0 = ra[lane], a1 = ra[32 + lane];
            acc0.x = fmaf(a0.x, wj, acc0.x); acc0.y = fmaf(a0.y, wj, acc0.y);
            acc0.z = fmaf(a0.z, wj, acc0.z); acc0.w = fmaf(a0.w, wj, acc0.w);
            acc1.x = fmaf(a1.x, wj, acc1.x); acc1.y = fmaf(a1.y, wj, acc1.y);
            acc1.z = fmaf(a1.z, wj, acc1.z); acc1.w = fmaf(a1.w, wj, acc1.w);
        }
    }
    float denom = warp_sum(wlocal) + 1e-6f;
    float inv = 1.f / denom;

    const float4* ns4 = (const float4*)&nsin[(size_t)n * HH];
    float4 r0 = ns4[lane], r1 = ns4[32 + lane];
    float x[8];
    x[0] = fmaf(acc0.x, inv, r0.x); x[1] = fmaf(acc0.y, inv, r0.y);
    x[2] = fmaf(acc0.z, inv, r0.z); x[3] = fmaf(acc0.w, inv, r0.w);
    x[4] = fmaf(acc1.x, inv, r1.x); x[5] = fmaf(acc1.y, inv, r1.y);
    x[6] = fmaf(acc1.z, inv, r1.z); x[7] = fmaf(acc1.w, inv, r1.w);

    float lsum = ((x[0] + x[1]) + (x[2] + x[3])) + ((x[4] + x[5]) + (x[6] + x[7]));
    float m = warp_sum(lsum) * (1.f / HH);
    float vsum = 0.f;
#pragma unroll
    for (int i = 0; i < 8; i++) {
        float d = x[i] - m;
        vsum = fmaf(d, d, vsum);
    }
    float var = warp_sum(vsum) * (1.f / HH);
    float rs = rsqrtf(var + 1e-5f);

    const float4* gg = (const float4*)&gamma[0];
    const float4* bb = (const float4*)&beta[0];
    float4 g0 = gg[lane], g1 = gg[32 + lane];
    float4 b0 = bb[lane], b1 = bb[32 + lane];
    float gam[8] = {g0.x, g0.y, g0.z, g0.w, g1.x, g1.y, g1.z, g1.w};
    float bet[8] = {b0.x, b0.y, b0.z, b0.w, b1.x, b1.y, b1.z, b1.w};
    float o[8];
#pragma unroll
    for (int i = 0; i < 8; i++) {
        float y = fmaf((x[i] - m) * rs, gam[i], bet[i]);
        o[i] = 0.5f * y * (1.f + erff(y * 0.70710678118654752440f));
    }
    float4* out4 = (float4*)&nsout[(size_t)n * HH];
    out4[lane] = make_float4(o[0], o[1], o[2], o[3]);
    out4[32 + lane] = make_float4(o[4], o[5], o[6], o[7]);
}

// ---------------- pooling ----------------
// exact softmax without max shift: tanh-bounded scores, |s| <= sum|score_w| -> exp safe
__global__ void pool_exp_kernel(const int* __restrict__ node_ids) {
    int i = blockIdx.x * blockDim.x + threadIdx.x;
    float e = 0.f;
    if (i < NN) {
        if (node_ids[i] != 0) e = expf(g_sp[i]);
        g_bv[i] = e;
    }
    float r = blk_sum(e);
    if (threadIdx.x == 0) atomicAdd(&g_pool_sum, r);
}

#define FCHUNK 64
__global__ __launch_bounds__(HH) void final_kernel(const float* __restrict__ ns, float* __restrict__ out) {
    int base = blockIdx.x * FCHUNK;
    int tid = threadIdx.x;
    float sum = g_pool_sum;
    float inv = (sum > 0.f) ? 1.f / sum : 0.f;
    if (tid < FCHUNK) {
        int n = base + tid;
        if (n < NN) out[HH + n] = g_bv[n] * inv;
    }
    int lim = min(FCHUNK, NN - base);
    float a0 = 0.f, a1 = 0.f, a2 = 0.f, a3 = 0.f;
    int i = 0;
    for (; i + 4 <= lim; i += 4) {
        float w0 = g_bv[base + i] * inv,     w1 = g_bv[base + i + 1] * inv;
        float w2 = g_bv[base + i + 2] * inv, w3 = g_bv[base + i + 3] * inv;
        float h0 = ns[(size_t)(base + i) * HH + tid];
        float h1 = ns[(size_t)(base + i + 1) * HH + tid];
        float h2 = ns[(size_t)(base + i + 2) * HH + tid];
        float h3 = ns[(size_t)(base + i + 3) * HH + tid];
        a0 = fmaf(w0, h0, a0); a1 = fmaf(w1, h1, a1);
        a2 = fmaf(w2, h2, a2); a3 = fmaf(w3, h3, a3);
    }
    for (; i < lim; i++)
        a0 = fmaf(g_bv[base + i] * inv, ns[(size_t)(base + i) * HH + tid], a0);
    atomicAdd(&out[tid], (a0 + a1) + (a2 + a3));
}

// ---------------- launcher (single stream, no device-state mutation) ----------------
extern "C" void kernel_launch(void* const* d_in, const int* in_sizes, int n_in,
                              void* d_out, int out_size) {
    const int*   node_ids = (const int*)d_in[0];
    const int*   edge_index = (const int*)d_in[1];
    const float* emb    = (const float*)d_in[2];
    const float* proj_w = (const float*)d_in[3];
    const float* edge_w = (const float*)d_in[4];
    const float* ln_g   = (const float*)d_in[5];
    const float* ln_b   = (const float*)d_in[6];
    const float* pool_w = (const float*)d_in[7];
    const float* pool_b = (const float*)d_in[8];
    const float* score_w = (const float*)d_in[9];
    float* out = (float*)d_out;
    const int* src = edge_index;
    const int* dst = edge_index + EE;

    float *p_ns, *p_ns2, *p_h, *p_a0, *p_b0, *p_a1, *p_b1, *p_sp;
    cudaGetSymbolAddress((void**)&p_ns, g_ns);
    cudaGetSymbolAddress((void**)&p_ns2, g_ns2);
    cudaGetSymbolAddress((void**)&p_h, g_h);
    cudaGetSymbolAddress((void**)&p_a0, g_a0);
    cudaGetSymbolAddress((void**)&p_b0, g_b0);
    cudaGetSymbolAddress((void**)&p_a1, g_a1);
    cudaGetSymbolAddress((void**)&p_b1, g_b1);
    cudaGetSymbolAddress((void**)&p_sp, g_sp);

    dim3 gemm_grid((NN + TM - 1) / TM, HH / TN);
    int wpn_grid = (NN + 7) / 8;

    init_kernel<<<(NN + 255) / 256, 256>>>(out);                                  // 1
    deg_kernel<<<(EE + 255) / 256, 256>>>(dst);                                   // 2
    embed_kernel<<<NN, HH>>>(node_ids, emb);                                      // 3
    sgemm_mma<0><<<gemm_grid, 256>>>(p_ns, proj_w, p_h, NN,                       // 4 (profiled)
                                     edge_w, edge_w + HH, p_a0, p_b0);
    scan_kernel<<<1, 1024>>>();                                                   // 5
    scatter_kernel<<<(EE + 255) / 256, 256>>>(src, dst);                          // 6
    agg_kernel<<<wpn_grid, 256>>>(p_h, p_ns, p_ns2, ln_g, ln_b, p_a0, p_b0);      // 7

    // layer 1
    sgemm_mma<0><<<gemm_grid, 256>>>(p_ns2, proj_w + HH * HH, p_h, NN,
                                     edge_w + 2 * HH, edge_w + 3 * HH, p_a1, p_b1);
    agg_kernel<<<wpn_grid, 256>>>(p_h, p_ns2, p_ns, ln_g + HH, ln_b + HH, p_a1, p_b1);

    // pooling: GEMM with fused tanh/score epilogue (no C write)
    sgemm_mma<1><<<gemm_grid, 256>>>(p_ns, pool_w, p_h, NN, pool_b, score_w, p_sp, nullptr);
    pool_exp_kernel<<<(NN + 255) / 256, 256>>>(node_ids);
    final_kernel<<<(NN + FCHUNK - 1) / FCHUNK, HH>>>(p_ns, out);
}

// round 16
// speedup vs baseline: 2.5655x; 1.0626x over previous
#include <cuda_runtime.h>
#include <cuda_bf16.h>
#include <math.h>
#include <stdint.h>

#define NN 20000
#define HH 256
#define EE 320000

// ---------------- scratch (device globals; no allocation allowed) ----------------
__device__ float g_ns[(size_t)NN * HH];
__device__ float g_ns2[(size_t)NN * HH];
__device__ float g_h[(size_t)NN * HH];
__device__ float g_a0[NN], g_b0[NN];   // layer0 edge-score halves
__device__ float g_a1[NN], g_b1[NN];   // layer1 edge-score halves
__device__ float g_sp[NN];             // pooling scores
__device__ float g_bv[NN];             // pooling exp weights
__device__ int   g_deg[NN];
__device__ int   g_rowptr[NN + 1];
__device__ int   g_cursor[NN];
__device__ int   g_src_s[EE];
__device__ float g_pool_sum;

__device__ __forceinline__ float blk_sum(float v) {
    __shared__ float sh[32];
    int lane = threadIdx.x & 31, w = threadIdx.x >> 5;
#pragma unroll
    for (int o = 16; o; o >>= 1) v += __shfl_down_sync(0xffffffffu, v, o);
    if (!lane) sh[w] = v;
    __syncthreads();
    int nw = blockDim.x >> 5;
    float r = (threadIdx.x < nw) ? sh[threadIdx.x] : 0.f;
    if (w == 0) {
#pragma unroll
        for (int o = 16; o; o >>= 1) r += __shfl_down_sync(0xffffffffu, r, o);
        if (!lane) sh[0] = r;
    }
    __syncthreads();
    r = sh[0];
    __syncthreads();
    return r;
}

__device__ __forceinline__ float warp_sum(float v) {
#pragma unroll
    for (int o = 16; o; o >>= 1) v += __shfl_xor_sync(0xffffffffu, v, o);
    return v;
}

// ---------------- setup kernels ----------------
__global__ void init_kernel(float* out) {
    int i = blockIdx.x * blockDim.x + threadIdx.x;
    if (i < NN) {
        g_deg[i] = 0;
        g_a0[i] = 0.f; g_b0[i] = 0.f;
        g_a1[i] = 0.f; g_b1[i] = 0.f;
        g_sp[i] = 0.f;
    }
    if (i < HH) out[i] = 0.f;
    if (i == 0) g_pool_sum = 0.f;
}

__global__ void deg_kernel(const int* __restrict__ dst) {
    int e = blockIdx.x * blockDim.x + threadIdx.x;
    if (e < EE) atomicAdd(&g_deg[dst[e]], 1);
}

__global__ void scan_kernel() {
    __shared__ int ssum[1024];
    const int CH = (NN + 1023) / 1024; // 20
    int tid = threadIdx.x;
    int start = tid * CH;
    int local[32];
    int s = 0;
#pragma unroll
    for (int i = 0; i < CH; i++) {
        int idx = start + i;
        int d = (idx < NN) ? g_deg[idx] : 0;
        local[i] = s;
        s += d;
    }
    ssum[tid] = s;
    __syncthreads();
    for (int off = 1; off < 1024; off <<= 1) {
        int v = 0;
        if (tid >= off) v = ssum[tid - off];
        __syncthreads();
        if (tid >= off) ssum[tid] += v;
        __syncthreads();
    }
    int prefix = ssum[tid] - s;
#pragma unroll
    for (int i = 0; i < CH; i++) {
        int idx = start + i;
        if (idx < NN) {
            int p = prefix + local[i];
            g_rowptr[idx] = p;
            g_cursor[idx] = p;
        }
    }
    if (tid == 1023) g_rowptr[NN] = ssum[1023];
}

__global__ void scatter_kernel(const int* __restrict__ src, const int* __restrict__ dst) {
    int e = blockIdx.x * blockDim.x + threadIdx.x;
    if (e < EE) {
        int d = dst[e];
        int pos = atomicAdd(&g_cursor[d], 1);
        g_src_s[pos] = src[e];
    }
}

// ---------------- TF32 mma.sync SGEMM, 3-stage cp.async (static 46KB), fused epilogues ----
// C[M,256] = A'[M,256] * B[256,256]^T where A'[r] = A[gather ? gather[r] : r].
// CTA 64x128, BK=16, 8 warps (2m x 4n), warp tile 32x32 of m16n8k8.
// MODE 0: write C and accumulate a[row]=C[row]·w1, b[row]=C[row]·w2 (edge MLP halves).
// MODE 1: no C write; accumulate s[row]=sum(tanh(C[row]+w1)*w2) (attention pooling).
#define SPAD 20
#define TM 64
#define TN 128

__device__ __forceinline__ void mma_tf32(float* c, const uint32_t* a, const uint32_t* b) {
    asm volatile(
        "mma.sync.aligned.m16n8k8.row.col.f32.tf32.tf32.f32 "
        "{%0,%1,%2,%3}, {%4,%5,%6,%7}, {%8,%9}, {%0,%1,%2,%3};"
        : "+f"(c[0]), "+f"(c[1]), "+f"(c[2]), "+f"(c[3])
        : "r"(a[0]), "r"(a[1]), "r"(a[2]), "r"(a[3]), "r"(b[0]), "r"(b[1]));
}

__device__ __forceinline__ void cp16(float* smem_dst, const float* gsrc, bool valid) {
    uint32_t s = (uint32_t)__cvta_generic_to_shared(smem_dst);
    int sz = valid ? 16 : 0;  // sz=0 -> 16B zero-fill
    asm volatile("cp.async.cg.shared.global [%0], [%1], 16, %2;"
                 :: "r"(s), "l"(gsrc), "r"(sz));
}

template <int MODE>
__global__ __launch_bounds__(256, 3) void sgemm_mma(const float* __restrict__ A,
                                                    const float* __restrict__ B,
                                                    float* __restrict__ C, int M,
                                                    const float* __restrict__ w1,
                                                    const float* __restrict__ w2,
                                                    float* __restrict__ accA,
                                                    float* __restrict__ accB,
                                                    const int* __restrict__ gather) {
    __shared__ float As[3][TM * SPAD];   // 15360 B
    __shared__ float Bs[3][TN * SPAD];   // 30720 B  (total 46080 B < 48 KB)
    const int tid = threadIdx.x;
    const int lane = tid & 31, w = tid >> 5;
    const int wm = w & 1, wn = w >> 1;     // warp grid 2 (m) x 4 (n)
    const int g = lane >> 2, t4 = lane & 3;
    const int bm = blockIdx.x * TM, bn = blockIdx.y * TN;

    float c[2][4][4];
#pragma unroll
    for (int mi = 0; mi < 2; mi++)
#pragma unroll
        for (int ni = 0; ni < 4; ni++)
#pragma unroll
            for (int j = 0; j < 4; j++) c[mi][ni][j] = 0.f;

    const int r0 = tid >> 2, q0 = tid & 3; // 64 rows x 4 quads = 256 slots
    const int ga0 = bm + r0;
    const bool v0 = ga0 < M;
    int arow = v0 ? ga0 : 0;
    if (gather) arow = gather[arow];       // layer-0: A row comes from emb[node_ids[r]]
    const float* pA0 = &A[(size_t)arow * HH + q0 * 4];
    const float* pB0 = &B[(size_t)(bn + r0) * HH + q0 * 4];
    const float* pB1 = &B[(size_t)(bn + r0 + 64) * HH + q0 * 4];
    const int soA = r0 * SPAD + q0 * 4;
    const int soB0 = r0 * SPAD + q0 * 4;
    const int soB1 = (r0 + 64) * SPAD + q0 * 4;

    // prologue: issue k-tiles 0 and 1 into stages 0 and 1
#pragma unroll
    for (int t = 0; t < 2; t++) {
        const int k0 = t * 16;
        cp16(&As[t][soA], pA0 + k0, v0);
        cp16(&Bs[t][soB0], pB0 + k0, true);
        cp16(&Bs[t][soB1], pB1 + k0, true);
        asm volatile("cp.async.commit_group;" ::: "memory");
    }

#pragma unroll 1
    for (int it = 0; it < 16; it++) {
        if (it < 15)
            asm volatile("cp.async.wait_group 1;" ::: "memory");
        else
            asm volatile("cp.async.wait_group 0;" ::: "memory");
        __syncthreads();   // also guarantees stage (it+2)%3 == (it-1)%3 is compute-done
        if (it + 2 < 16) {
            const int st2 = (it + 2) % 3;
            const int k0 = (it + 2) * 16;
            cp16(&As[st2][soA], pA0 + k0, v0);
            cp16(&Bs[st2][soB0], pB0 + k0, true);
            cp16(&Bs[st2][soB1], pB1 + k0, true);
            asm volatile("cp.async.commit_group;" ::: "memory");
        }
        const int st = it % 3;
        const uint32_t* Asb = (const uint32_t*)&As[st][0];
        const uint32_t* Bsb = (const uint32_t*)&Bs[st][0];
#pragma unroll
        for (int ks = 0; ks < 2; ks++) {
            const int kb = ks * 8 + t4;
            uint32_t af[2][4];
#pragma unroll
            for (int mi = 0; mi < 2; mi++) {
                const int rr = wm * 32 + mi * 16 + g;
                af[mi][0] = Asb[rr * SPAD + kb];
                af[mi][1] = Asb[(rr + 8) * SPAD + kb];
                af[mi][2] = Asb[rr * SPAD + kb + 4];
                af[mi][3] = Asb[(rr + 8) * SPAD + kb + 4];
            }
            uint32_t bf[4][2];
#pragma unroll
            for (int ni = 0; ni < 4; ni++) {
                const int cc = wn * 32 + ni * 8 + g;
                bf[ni][0] = Bsb[cc * SPAD + kb];
                bf[ni][1] = Bsb[cc * SPAD + kb + 4];
            }
#pragma unroll
            for (int mi = 0; mi < 2; mi++)
#pragma unroll
                for (int ni = 0; ni < 4; ni++)
                    mma_tf32(c[mi][ni], af[mi], bf[ni]);
        }
    }

    // epilogue: C write (MODE 0) + fused row reductions
#pragma unroll
    for (int mi = 0; mi < 2; mi++) {
        const int row = bm + wm * 32 + mi * 16 + g;
        float palo = 0.f, pahi = 0.f, pblo = 0.f, pbhi = 0.f;
#pragma unroll
        for (int ni = 0; ni < 4; ni++) {
            const int col = bn + wn * 32 + ni * 8 + 2 * t4;
            if (MODE == 0) {
                const float e0 = __ldg(&w1[col]), e1 = __ldg(&w1[col + 1]);
                const float f0 = __ldg(&w2[col]), f1 = __ldg(&w2[col + 1]);
                palo += c[mi][ni][0] * e0 + c[mi][ni][1] * e1;
                pahi += c[mi][ni][2] * e0 + c[mi][ni][3] * e1;
                pblo += c[mi][ni][0] * f0 + c[mi][ni][1] * f1;
                pbhi += c[mi][ni][2] * f0 + c[mi][ni][3] * f1;
                if (row < M)
                    *(float2*)&C[(size_t)row * HH + col] = make_float2(c[mi][ni][0], c[mi][ni][1]);
                if (row + 8 < M)
                    *(float2*)&C[(size_t)(row + 8) * HH + col] = make_float2(c[mi][ni][2], c[mi][ni][3]);
            } else {
                const float p0 = __ldg(&w1[col]), p1 = __ldg(&w1[col + 1]);
                const float s0 = __ldg(&w2[col]), s1 = __ldg(&w2[col + 1]);
                palo += tanhf(c[mi][ni][0] + p0) * s0 + tanhf(c[mi][ni][1] + p1) * s1;
                pahi += tanhf(c[mi][ni][2] + p0) * s0 + tanhf(c[mi][ni][3] + p1) * s1;
            }
        }
        palo += __shfl_xor_sync(0xffffffffu, palo, 1);
        palo += __shfl_xor_sync(0xffffffffu, palo, 2);
        pahi += __shfl_xor_sync(0xffffffffu, pahi, 1);
        pahi += __shfl_xor_sync(0xffffffffu, pahi, 2);
        if (MODE == 0) {
            pblo += __shfl_xor_sync(0xffffffffu, pblo, 1);
            pblo += __shfl_xor_sync(0xffffffffu, pblo, 2);
            pbhi += __shfl_xor_sync(0xffffffffu, pbhi, 1);
            pbhi += __shfl_xor_sync(0xffffffffu, pbhi, 2);
        }
        if (t4 == 0) {
            if (row < M) {
                atomicAdd(&accA[row], palo);
                if (MODE == 0) atomicAdd(&accB[row], pblo);
            }
            if (row + 8 < M) {
                atomicAdd(&accA[row + 8], pahi);
                if (MODE == 0) atomicAdd(&accB[row + 8], pbhi);
            }
        }
    }
}

// ---------------- per-layer kernels ----------------
// warp-per-node fused aggregation: inline softmax weights (global max cancels
// up to the +1e-6 term, ~1e-7 relative), weighted gather-sum, residual, LN, GELU.
// gather != nullptr (layer 0): residual row n comes from nsin[gather[n]] (= emb[node_ids[n]]).
__global__ __launch_bounds__(256) void agg_kernel(const float* __restrict__ hbuf,
                                                  const float* __restrict__ nsin,
                                                  float* __restrict__ nsout,
                                                  const float* __restrict__ gamma,
                                                  const float* __restrict__ beta,
                                                  const float* __restrict__ av,
                                                  const float* __restrict__ bv,
                                                  const int* __restrict__ gather) {
    int wid = threadIdx.x >> 5, lane = threadIdx.x & 31;
    int n = blockIdx.x * 8 + wid;
    if (n >= NN) return;
    int beg = g_rowptr[n], end = g_rowptr[n + 1];
    float bvn = bv[n];

    float4 acc0 = make_float4(0.f, 0.f, 0.f, 0.f);
    float4 acc1 = make_float4(0.f, 0.f, 0.f, 0.f);
    float wlocal = 0.f;

    for (int base = beg; base < end; base += 32) {
        int cnt = min(32, end - base);
        int sv = 0;
        float wv = 0.f;
        if (lane < cnt) {
            sv = g_src_s[base + lane];
            float sc = av[sv] + bvn;
            sc = (sc >= 0.f) ? sc : 0.2f * sc;
            wv = expf(sc);
        }
        wlocal += wv;
        int j = 0;
        for (; j + 2 <= cnt; j += 2) {
            int   sj0 = __shfl_sync(0xffffffffu, sv, j);
            int   sj1 = __shfl_sync(0xffffffffu, sv, j + 1);
            float wj0 = __shfl_sync(0xffffffffu, wv, j);
            float wj1 = __shfl_sync(0xffffffffu, wv, j + 1);
            const float4* ra = (const float4*)&hbuf[(size_t)sj0 * HH];
            const float4* rb = (const float4*)&hbuf[(size_t)sj1 * HH];
            float4 a0 = ra[lane], a1 = ra[32 + lane];
            float4 b0 = rb[lane], b1 = rb[32 + lane];
            acc0.x = fmaf(a0.x, wj0, acc0.x); acc0.y = fmaf(a0.y, wj0, acc0.y);
            acc0.z = fmaf(a0.z, wj0, acc0.z); acc0.w = fmaf(a0.w, wj0, acc0.w);
            acc1.x = fmaf(a1.x, wj0, acc1.x); acc1.y = fmaf(a1.y, wj0, acc1.y);
            acc1.z = fmaf(a1.z, wj0, acc1.z); acc1.w = fmaf(a1.w, wj0, acc1.w);
            acc0.x = fmaf(b0.x, wj1, acc0.x); acc0.y = fmaf(b0.y, wj1, acc0.y);
            acc0.z = fmaf(b0.z, wj1, acc0.z); acc0.w = fmaf(b0.w, wj1, acc0.w);
            acc1.x = fmaf(b1.x, wj1, acc1.x); acc1.y = fmaf(b1.y, wj1, acc1.y);
            acc1.z = fmaf(b1.z, wj1, acc1.z); acc1.w = fmaf(b1.w, wj1, acc1.w);
        }
        if (j < cnt) {
            int   sj = __shfl_sync(0xffffffffu, sv, j);
            float wj = __shfl_sync(0xffffffffu, wv, j);
            const float4* ra = (const float4*)&hbuf[(size_t)sj * HH];
            float4 a0 = ra[lane], a1 = ra[32 + lane];
            acc0.x = fmaf(a0.x, wj, acc0.x); acc0.y = fmaf(a0.y, wj, acc0.y);
            acc0.z = fmaf(a0.z, wj, acc0.z); acc0.w = fmaf(a0.w, wj, acc0.w);
            acc1.x = fmaf(a1.x, wj, acc1.x); acc1.y = fmaf(a1.y, wj, acc1.y);
            acc1.z = fmaf(a1.z, wj, acc1.z); acc1.w = fmaf(a1.w, wj, acc1.w);
        }
    }
    float denom = warp_sum(wlocal) + 1e-6f;
    float inv = 1.f / denom;

    int nr = gather ? gather[n] : n;
    const float4* ns4 = (const float4*)&nsin[(size_t)nr * HH];
    float4 r0 = ns4[lane], r1 = ns4[32 + lane];
    float x[8];
    x[0] = fmaf(acc0.x, inv, r0.x); x[1] = fmaf(acc0.y, inv, r0.y);
    x[2] = fmaf(acc0.z, inv, r0.z); x[3] = fmaf(acc0.w, inv, r0.w);
    x[4] = fmaf(acc1.x, inv, r1.x); x[5] = fmaf(acc1.y, inv, r1.y);
    x[6] = fmaf(acc1.z, inv, r1.z); x[7] = fmaf(acc1.w, inv, r1.w);

    float lsum = ((x[0] + x[1]) + (x[2] + x[3])) + ((x[4] + x[5]) + (x[6] + x[7]));
    float m = warp_sum(lsum) * (1.f / HH);
    float vsum = 0.f;
#pragma unroll
    for (int i = 0; i < 8; i++) {
        float d = x[i] - m;
        vsum = fmaf(d, d, vsum);
    }
    float var = warp_sum(vsum) * (1.f / HH);
    float rs = rsqrtf(var + 1e-5f);

    const float4* gg = (const float4*)&gamma[0];
    const float4* bb = (const float4*)&beta[0];
    float4 g0 = gg[lane], g1 = gg[32 + lane];
    float4 b0 = bb[lane], b1 = bb[32 + lane];
    float gam[8] = {g0.x, g0.y, g0.z, g0.w, g1.x, g1.y, g1.z, g1.w};
    float bet[8] = {b0.x, b0.y, b0.z, b0.w, b1.x, b1.y, b1.z, b1.w};
    float o[8];
#pragma unroll
    for (int i = 0; i < 8; i++) {
        float y = fmaf((x[i] - m) * rs, gam[i], bet[i]);
        o[i] = 0.5f * y * (1.f + erff(y * 0.70710678118654752440f));
    }
    float4* out4 = (float4*)&nsout[(size_t)n * HH];
    out4[lane] = make_float4(o[0], o[1], o[2], o[3]);
    out4[32 + lane] = make_float4(o[4], o[5], o[6], o[7]);
}

// ---------------- pooling ----------------
// exact softmax without max shift: tanh-bounded scores, |s| <= sum|score_w| -> exp safe
__global__ void pool_exp_kernel(const int* __restrict__ node_ids) {
    int i = blockIdx.x * blockDim.x + threadIdx.x;
    float e = 0.f;
    if (i < NN) {
        if (node_ids[i] != 0) e = expf(g_sp[i]);
        g_bv[i] = e;
    }
    float r = blk_sum(e);
    if (threadIdx.x == 0) atomicAdd(&g_pool_sum, r);
}

#define FCHUNK 64
__global__ __launch_bounds__(HH) void final_kernel(const float* __restrict__ ns, float* __restrict__ out) {
    int base = blockIdx.x * FCHUNK;
    int tid = threadIdx.x;
    float sum = g_pool_sum;
    float inv = (sum > 0.f) ? 1.f / sum : 0.f;
    if (tid < FCHUNK) {
        int n = base + tid;
        if (n < NN) out[HH + n] = g_bv[n] * inv;
    }
    int lim = min(FCHUNK, NN - base);
    float a0 = 0.f, a1 = 0.f, a2 = 0.f, a3 = 0.f;
    int i = 0;
    for (; i + 4 <= lim; i += 4) {
        float w0 = g_bv[base + i] * inv,     w1 = g_bv[base + i + 1] * inv;
        float w2 = g_bv[base + i + 2] * inv, w3 = g_bv[base + i + 3] * inv;
        float h0 = ns[(size_t)(base + i) * HH + tid];
        float h1 = ns[(size_t)(base + i + 1) * HH + tid];
        float h2 = ns[(size_t)(base + i + 2) * HH + tid];
        float h3 = ns[(size_t)(base + i + 3) * HH + tid];
        a0 = fmaf(w0, h0, a0); a1 = fmaf(w1, h1, a1);
        a2 = fmaf(w2, h2, a2); a3 = fmaf(w3, h3, a3);
    }
    for (; i < lim; i++)
        a0 = fmaf(g_bv[base + i] * inv, ns[(size_t)(base + i) * HH + tid], a0);
    atomicAdd(&out[tid], (a0 + a1) + (a2 + a3));
}

// ---------------- launcher (single stream, no device-state mutation) ----------------
extern "C" void kernel_launch(void* const* d_in, const int* in_sizes, int n_in,
                              void* d_out, int out_size) {
    const int*   node_ids = (const int*)d_in[0];
    const int*   edge_index = (const int*)d_in[1];
    const float* emb    = (const float*)d_in[2];
    const float* proj_w = (const float*)d_in[3];
    const float* edge_w = (const float*)d_in[4];
    const float* ln_g   = (const float*)d_in[5];
    const float* ln_b   = (const float*)d_in[6];
    const float* pool_w = (const float*)d_in[7];
    const float* pool_b = (const float*)d_in[8];
    const float* score_w = (const float*)d_in[9];
    float* out = (float*)d_out;
    const int* src = edge_index;
    const int* dst = edge_index + EE;

    float *p_ns, *p_ns2, *p_h, *p_a0, *p_b0, *p_a1, *p_b1, *p_sp;
    cudaGetSymbolAddress((void**)&p_ns, g_ns);
    cudaGetSymbolAddress((void**)&p_ns2, g_ns2);
    cudaGetSymbolAddress((void**)&p_h, g_h);
    cudaGetSymbolAddress((void**)&p_a0, g_a0);
    cudaGetSymbolAddress((void**)&p_b0, g_b0);
    cudaGetSymbolAddress((void**)&p_a1, g_a1);
    cudaGetSymbolAddress((void**)&p_b1, g_b1);
    cudaGetSymbolAddress((void**)&p_sp, g_sp);

    dim3 gemm_grid((NN + TM - 1) / TM, HH / TN);
    int wpn_grid = (NN + 7) / 8;

    // layer 0: GEMM0 gathers A rows directly from emb via node_ids (no embed pass)
    init_kernel<<<(NN + 255) / 256, 256>>>(out);                                  // 1
    deg_kernel<<<(EE + 255) / 256, 256>>>(dst);                                   // 2
    sgemm_mma<0><<<gemm_grid, 256>>>(emb, proj_w, p_h, NN,                        // 3
                                     edge_w, edge_w + HH, p_a0, p_b0, node_ids);
    scan_kernel<<<1, 1024>>>();                                                   // 4
    scatter_kernel<<<(EE + 255) / 256, 256>>>(src, dst);                          // 5
    agg_kernel<<<wpn_grid, 256>>>(p_h, emb, p_ns2, ln_g, ln_b, p_a0, p_b0,        // 6
                                  node_ids);

    // layer 1
    sgemm_mma<0><<<gemm_grid, 256>>>(p_ns2, proj_w + HH * HH, p_h, NN,
                                     edge_w + 2 * HH, edge_w + 3 * HH, p_a1, p_b1, nullptr);
    agg_kernel<<<wpn_grid, 256>>>(p_h, p_ns2, p_ns, ln_g + HH, ln_b + HH, p_a1, p_b1, nullptr);

    // pooling: GEMM with fused tanh/score epilogue (no C write)
    sgemm_mma<1><<<gemm_grid, 256>>>(p_ns, pool_w, p_h, NN, pool_b, score_w, p_sp, nullptr, nullptr);
    pool_exp_kernel<<<(NN + 255) / 256, 256>>>(node_ids);
    final_kernel<<<(NN + FCHUNK - 1) / FCHUNK, HH>>>(p_ns, out);
}